// round 14
// baseline (speedup 1.0000x reference)
#include <cuda_runtime.h>
#include <cuda_fp16.h>
#include <cstdint>
#include <cstddef>

#define BB 128
#define NL 64
#define EE 131072
#define NN 8192
#define KD 4096

// -------------------- device scratch --------------------
__device__ float g_h5 [NN * 64];
__device__ float g_e1 [EE * 256];      // cat[t1|t2|X3|Y4]
__device__ float g_mm [EE * 64];       // tmp_mm result
__device__ float g_ct [64 * EE];       // CoutT
__device__ float g_agg[NN * 64];
__device__ float g_n1 [NN * 256];
__device__ float g_wcat[64 * 256];     // [W1|W2|W3|W4]
__device__ uint2 g_we1p[128 * 256];    // We1 split-fp16 pairs: [k-pair][col]
__device__ uint2 g_we2p[128 * 64];     // We2 split-fp16 pairs
__device__ int   g_adj[BB * NL * NL];

// -------------------- mma helpers --------------------
__device__ __forceinline__ void mma16(float* c, const uint32_t* a, const uint32_t* b) {
    asm volatile(
        "mma.sync.aligned.m16n8k16.row.col.f32.f16.f16.f32 "
        "{%0,%1,%2,%3}, {%4,%5,%6,%7}, {%8,%9}, {%0,%1,%2,%3};"
        : "+f"(c[0]), "+f"(c[1]), "+f"(c[2]), "+f"(c[3])
        : "r"(a[0]), "r"(a[1]), "r"(a[2]), "r"(a[3]), "r"(b[0]), "r"(b[1]));
}
__device__ __forceinline__ void split2(float x, float y, uint32_t& h, uint32_t& l) {
    __half2 hh = __floats2half2_rn(x, y);
    float2 hf = __half22float2(hh);
    __half2 ll = __floats2half2_rn(x - hf.x, y - hf.y);
    h = *(uint32_t*)&hh;
    l = *(uint32_t*)&ll;
}

// ==================== split-FP16 3-term mma.sync GEMM (standalone) ====================
#define APAD2 36

template<int NT>
__global__ void __launch_bounds__(256, 2) k_gemm_f16(const float* __restrict__ A,
                                                     const float* __restrict__ B,
                                                     float* __restrict__ C,
                                                     int M, int N, int K) {
    constexpr int BPAD2 = (NT == 64) ? 72 : 136;
    constexpr int NTW = NT / 16;
    __shared__ uint32_t As2[128][APAD2];
    __shared__ uint32_t Bs2[32][BPAD2];
    const int tid = threadIdx.x;
    const int lane = tid & 31, wid = tid >> 5;
    const int wm = wid & 3, wn = wid >> 2;
    const int g = lane >> 2, q = lane & 3;
    const int m0 = blockIdx.x * 128, n0 = blockIdx.y * NT;

    const int ar = tid >> 3;
    const int ac = (tid & 7) * 4;
    const int ap = ac >> 1;
    constexpr int BTPR = NT / 4;
    const int bp = tid / BTPR;
    const int bn = (tid % BTPR) * 4;

    float acc[2][NTW][4] = {};

    for (int k0 = 0; k0 < K; k0 += 32) {
#pragma unroll
        for (int i = 0; i < 4; i++) {
            const int row = ar + i * 32;
            float4 v = *(const float4*)(A + (size_t)(m0 + row) * K + k0 + ac);
            uint32_t h01, l01, h23, l23;
            split2(v.x, v.y, h01, l01);
            split2(v.z, v.w, h23, l23);
            As2[row][ap]      = h01;
            As2[row][ap + 1]  = h23;
            As2[row][ap + 16] = l01;
            As2[row][ap + 17] = l23;
        }
#pragma unroll
        for (int it = 0; it < NT / 64; it++) {
            const int p = bp + it * 8;
            const float* r0p = B + (size_t)(k0 + 2 * p) * N + n0 + bn;
            float4 r0 = *(const float4*)(r0p);
            float4 r1 = *(const float4*)(r0p + N);
            uint32_t h, l;
            split2(r0.x, r1.x, h, l); Bs2[p][bn]     = h; Bs2[p + 16][bn]     = l;
            split2(r0.y, r1.y, h, l); Bs2[p][bn + 1] = h; Bs2[p + 16][bn + 1] = l;
            split2(r0.z, r1.z, h, l); Bs2[p][bn + 2] = h; Bs2[p + 16][bn + 2] = l;
            split2(r0.w, r1.w, h, l); Bs2[p][bn + 3] = h; Bs2[p + 16][bn + 3] = l;
        }
        __syncthreads();

#pragma unroll
        for (int s = 0; s < 2; s++) {
            uint32_t ah[2][4], al[2][4];
#pragma unroll
            for (int mt = 0; mt < 2; mt++) {
                const int row = wm * 32 + mt * 16 + g;
                ah[mt][0] = As2[row][s * 8 + q];
                ah[mt][1] = As2[row + 8][s * 8 + q];
                ah[mt][2] = As2[row][s * 8 + q + 4];
                ah[mt][3] = As2[row + 8][s * 8 + q + 4];
                al[mt][0] = As2[row][16 + s * 8 + q];
                al[mt][1] = As2[row + 8][16 + s * 8 + q];
                al[mt][2] = As2[row][16 + s * 8 + q + 4];
                al[mt][3] = As2[row + 8][16 + s * 8 + q + 4];
            }
#pragma unroll
            for (int nt = 0; nt < NTW; nt++) {
                const int col = wn * (NT / 2) + nt * 8 + g;
                uint32_t bh[2], bl[2];
                bh[0] = Bs2[s * 8 + q][col];
                bh[1] = Bs2[s * 8 + q + 4][col];
                bl[0] = Bs2[16 + s * 8 + q][col];
                bl[1] = Bs2[16 + s * 8 + q + 4][col];
#pragma unroll
                for (int mt = 0; mt < 2; mt++) {
                    mma16(acc[mt][nt], ah[mt], bh);
                    mma16(acc[mt][nt], ah[mt], bl);
                    mma16(acc[mt][nt], al[mt], bh);
                }
            }
        }
        __syncthreads();
    }

#pragma unroll
    for (int mt = 0; mt < 2; mt++) {
        const int row = m0 + wm * 32 + mt * 16 + g;
#pragma unroll
        for (int nt = 0; nt < NTW; nt++) {
            const int col = n0 + wn * (NT / 2) + nt * 8 + q * 2;
            *(float2*)(C + (size_t)row * N + col) =
                make_float2(acc[mt][nt][0], acc[mt][nt][1]);
            *(float2*)(C + (size_t)(row + 8) * N + col) =
                make_float2(acc[mt][nt][2], acc[mt][nt][3]);
        }
    }
}

// ==================== fused edge MLP, 512 thr ====================
// GEMM1: A double-buffered in SMEM; B (We1) fragments via __ldg from g_we1p.
// SMEM words: As2 2x128x36 | hid 128x264 | rstat 256 | gb 512
#define HIDS 264
#define SM_AS2 0
#define SM_HID 9216
#define SM_RST (SM_HID + 128 * HIDS)
#define SM_GB  (SM_RST + 256)
#define SM_EDGE_WORDS (SM_GB + 512)
#define SMEM_EDGE (SM_EDGE_WORDS * 4)
#define TS 132

__global__ void __launch_bounds__(512) k_edge_mlp(const float* __restrict__ Cin,
                                                  const float* __restrict__ cat,
                                                  const float* __restrict__ h5,
                                                  const float* __restrict__ mm,
                                                  const int* __restrict__ EI,
                                                  const uint2* __restrict__ B1,
                                                  const uint2* __restrict__ B2,
                                                  float* __restrict__ Cout,
                                                  float* __restrict__ CoutT,
                                                  const float* __restrict__ gam,
                                                  const float* __restrict__ bet) {
    extern __shared__ uint32_t sm[];
    uint32_t (*As2)[128][36] = (uint32_t(*)[128][36])(sm + SM_AS2);
    uint32_t* hidw = sm + SM_HID;
    float*    hidf = (float*)hidw;
    float*    rstat = (float*)(sm + SM_RST);
    float*    gb    = (float*)(sm + SM_GB);

    const int tid = threadIdx.x;
    const int lane = tid & 31, wid = tid >> 5;   // 16 warps
    const int wm = wid & 3, wn = wid >> 2;       // 4 x 4
    const int g = lane >> 2, q = lane & 3;
    const int m0 = blockIdx.x * 128;

    if (tid < 256) {
        gb[2 * tid]     = gam[tid];
        gb[2 * tid + 1] = bet[tid];
    }

    // A loader: one row per 4 threads, 8 k-values per thread
    const int ar = tid >> 2;            // 0..127
    const int ac = (tid & 3) * 8;       // 0,8,16,24
    const int ap = ac >> 1;             // 0,4,8,12

    int sl;
    {
        const int e = m0 + ar;
        const int s = EI[EE + e], d = EI[2 * EE + e];
        sl = (s == d) ? s : -1;
    }

    // A synthesis + split for chunk c into buffer buf
    auto stageA = [&](int c, int buf) {
        const int k0 = c * 32;
        const size_t e = (size_t)(m0 + ar);
        float4 v0, v1;
        if (c < 2) {
            const float* p = Cin + e * 64 + k0 + ac;
            v0 = *(const float4*)(p);
            v1 = *(const float4*)(p + 4);
        } else if (c < 4) {
            const float* p1 = cat + e * 256 + (k0 - 64) + ac;
            const float* p2 = p1 + 64;
            float4 a0 = *(const float4*)(p1);
            float4 a1 = *(const float4*)(p1 + 4);
            float4 b0 = *(const float4*)(p2);
            float4 b1 = *(const float4*)(p2 + 4);
            v0 = make_float4(a0.x * b0.x, a0.y * b0.y, a0.z * b0.z, a0.w * b0.w);
            v1 = make_float4(a1.x * b1.x, a1.y * b1.y, a1.z * b1.z, a1.w * b1.w);
        } else if (c < 6) {
            if (sl >= 0) {
                const float* p = h5 + (size_t)sl * 64 + (k0 - 128) + ac;
                v0 = *(const float4*)(p);
                v1 = *(const float4*)(p + 4);
            } else {
                v0 = make_float4(0.f, 0.f, 0.f, 0.f);
                v1 = v0;
            }
        } else {
            const float* p = mm + e * 64 + (k0 - 192) + ac;
            v0 = *(const float4*)(p);
            v1 = *(const float4*)(p + 4);
        }
        uint32_t h, l;
        split2(v0.x, v0.y, h, l); As2[buf][ar][ap]      = h; As2[buf][ar][ap + 16] = l;
        split2(v0.z, v0.w, h, l); As2[buf][ar][ap + 1]  = h; As2[buf][ar][ap + 17] = l;
        split2(v1.x, v1.y, h, l); As2[buf][ar][ap + 2]  = h; As2[buf][ar][ap + 18] = l;
        split2(v1.z, v1.w, h, l); As2[buf][ar][ap + 3]  = h; As2[buf][ar][ap + 19] = l;
    };

    // ---------------- GEMM1: hidden = tmp @ We1, single pass, N=256 ----------------
    float acc[2][8][4] = {};
    stageA(0, 0);
    __syncthreads();
#pragma unroll 1
    for (int c = 0; c < 8; c++) {
        const int buf = c & 1;
        if (c < 7) stageA(c + 1, buf ^ 1);
#pragma unroll
        for (int s = 0; s < 2; s++) {
            const int P = c * 16 + s * 8;        // global pair-row base
            uint32_t ah[2][4], al[2][4];
#pragma unroll
            for (int mt = 0; mt < 2; mt++) {
                const int row = wm * 32 + mt * 16 + g;
                ah[mt][0] = As2[buf][row][s * 8 + q];
                ah[mt][1] = As2[buf][row + 8][s * 8 + q];
                ah[mt][2] = As2[buf][row][s * 8 + q + 4];
                ah[mt][3] = As2[buf][row + 8][s * 8 + q + 4];
                al[mt][0] = As2[buf][row][16 + s * 8 + q];
                al[mt][1] = As2[buf][row + 8][16 + s * 8 + q];
                al[mt][2] = As2[buf][row][16 + s * 8 + q + 4];
                al[mt][3] = As2[buf][row + 8][16 + s * 8 + q + 4];
            }
#pragma unroll
            for (int nt = 0; nt < 8; nt++) {
                const int col = wn * 64 + nt * 8 + g;
                uint2 u0 = __ldg(&B1[(size_t)(P + q) * 256 + col]);
                uint2 u1 = __ldg(&B1[(size_t)(P + q + 4) * 256 + col]);
                uint32_t bh[2] = {u0.x, u1.x};
                uint32_t bl[2] = {u0.y, u1.y};
#pragma unroll
                for (int mt = 0; mt < 2; mt++) {
                    mma16(acc[mt][nt], ah[mt], bh);
                    mma16(acc[mt][nt], ah[mt], bl);
                    mma16(acc[mt][nt], al[mt], bh);
                }
            }
        }
        __syncthreads();
    }
    // park raw hidden
#pragma unroll
    for (int mt = 0; mt < 2; mt++) {
        const int row = wm * 32 + mt * 16 + g;
#pragma unroll
        for (int nt = 0; nt < 8; nt++) {
            const int col = wn * 64 + nt * 8 + 2 * q;
            *(float2*)(hidf + (size_t)row * HIDS + col) =
                make_float2(acc[mt][nt][0], acc[mt][nt][1]);
            *(float2*)(hidf + (size_t)(row + 8) * HIDS + col) =
                make_float2(acc[mt][nt][2], acc[mt][nt][3]);
        }
    }
    __syncthreads();

    // ---------------- LN stats: 8 rows per warp ----------------
#pragma unroll 1
    for (int rr = 0; rr < 8; rr++) {
        const int row = wid * 8 + rr;
        float s1 = 0.f, s2 = 0.f;
#pragma unroll
        for (int j = 0; j < 8; j++) {
            float v = hidf[(size_t)row * HIDS + lane + 32 * j];
            s1 += v; s2 += v * v;
        }
#pragma unroll
        for (int o = 16; o > 0; o >>= 1) {
            s1 += __shfl_xor_sync(0xffffffffu, s1, o);
            s2 += __shfl_xor_sync(0xffffffffu, s2, o);
        }
        if (lane == 0) {
            float mu = s1 * (1.0f / 256.0f);
            float var = fmaxf(s2 * (1.0f / 256.0f) - mu * mu, 0.f);
            rstat[2 * row]     = mu;
            rstat[2 * row + 1] = rsqrtf(var + 1e-5f);
        }
    }
    __syncthreads();

    // ---------------- LN + GELU + split-pack, in place ----------------
#pragma unroll 1
    for (int i = 0; i < 32; i++) {
        const int idx = i * 512 + tid;
        const int r = idx >> 7, p = idx & 127;
        float2 v = *(float2*)(hidf + (size_t)r * HIDS + 2 * p);
        const float mu = rstat[2 * r], rs = rstat[2 * r + 1];
        float4 gbv = *(float4*)(gb + 4 * p);
        float y0 = (v.x - mu) * rs * gbv.x + gbv.y;
        float y1 = (v.y - mu) * rs * gbv.z + gbv.w;
        y0 = 0.5f * y0 * (1.0f + erff(y0 * 0.70710678118654752440f));
        y1 = 0.5f * y1 * (1.0f + erff(y1 * 0.70710678118654752440f));
        uint32_t h, l;
        split2(y0, y1, h, l);
        hidw[(size_t)r * HIDS + 2 * p]     = h;
        hidw[(size_t)r * HIDS + 2 * p + 1] = l;
    }
    __syncthreads();

    // ---------------- GEMM2: Cout = hidden @ We2 (K=256, N=64) ----------------
    float acc2[2][2][4] = {};
#pragma unroll 1
    for (int s = 0; s < 16; s++) {
        uint32_t ah[2][4], al[2][4];
#pragma unroll
        for (int mt = 0; mt < 2; mt++) {
            const int row = wm * 32 + mt * 16 + g;
            uint2 t0 = *(uint2*)(hidw + (size_t)row * HIDS + 16 * s + 2 * q);
            uint2 t1 = *(uint2*)(hidw + (size_t)(row + 8) * HIDS + 16 * s + 2 * q);
            uint2 t2 = *(uint2*)(hidw + (size_t)row * HIDS + 16 * s + 2 * q + 8);
            uint2 t3 = *(uint2*)(hidw + (size_t)(row + 8) * HIDS + 16 * s + 2 * q + 8);
            ah[mt][0] = t0.x; al[mt][0] = t0.y;
            ah[mt][1] = t1.x; al[mt][1] = t1.y;
            ah[mt][2] = t2.x; al[mt][2] = t2.y;
            ah[mt][3] = t3.x; al[mt][3] = t3.y;
        }
#pragma unroll
        for (int nt = 0; nt < 2; nt++) {
            const int col = wn * 16 + nt * 8 + g;
            uint2 u0 = __ldg(&B2[(8 * s + q) * 64 + col]);
            uint2 u1 = __ldg(&B2[(8 * s + q + 4) * 64 + col]);
            uint32_t bh[2] = {u0.x, u1.x};
            uint32_t bl[2] = {u0.y, u1.y};
#pragma unroll
            for (int mt = 0; mt < 2; mt++) {
                mma16(acc2[mt][nt], ah[mt], bh);
                mma16(acc2[mt][nt], ah[mt], bl);
                mma16(acc2[mt][nt], al[mt], bh);
            }
        }
    }
    __syncthreads();   // done reading hidw; reuse as transpose tile

    float* T = (float*)(sm + SM_HID);   // [64][TS]
#pragma unroll
    for (int mt = 0; mt < 2; mt++) {
        const int rloc = wm * 32 + mt * 16 + g;
        const int row = m0 + rloc;
#pragma unroll
        for (int nt = 0; nt < 2; nt++) {
            const int col = wn * 16 + nt * 8 + 2 * q;
            *(float2*)(Cout + (size_t)row * 64 + col) =
                make_float2(acc2[mt][nt][0], acc2[mt][nt][1]);
            *(float2*)(Cout + (size_t)(row + 8) * 64 + col) =
                make_float2(acc2[mt][nt][2], acc2[mt][nt][3]);
            T[col * TS + rloc]           = acc2[mt][nt][0];
            T[(col + 1) * TS + rloc]     = acc2[mt][nt][1];
            T[col * TS + rloc + 8]       = acc2[mt][nt][2];
            T[(col + 1) * TS + rloc + 8] = acc2[mt][nt][3];
        }
    }
    __syncthreads();
#pragma unroll
    for (int i = 0; i < 16; i++) {
        const int idx = i * 512 + tid;
        const int k = idx >> 7, r = idx & 127;
        CoutT[(size_t)k * EE + m0 + r] = T[k * TS + r];
    }
}

// ==================== fused Conv_agg, 512 threads (16 warps, 4m x 4n) ==========
#define CA_ADJ 0
#define CA_XS  4096
#define CA_WRC 8448
#define CA_ZCF 16896
#define CA_ZCB 25344
#define CA_GC  34048
#define CA_WORDS 42496
#define SMEM_CAGG (CA_WORDS * 4)

__global__ void __launch_bounds__(512) k_cagg(const float* __restrict__ x,
                                              const float* __restrict__ Wagg,
                                              const float* __restrict__ CoutT,
                                              float* __restrict__ agg) {
    extern __shared__ uint32_t sm[];
    int* adjs = (int*)(sm + CA_ADJ);
    uint32_t (*Xs)[68]   = (uint32_t(*)[68])(sm + CA_XS);
    uint32_t (*Wrc)[132] = (uint32_t(*)[132])(sm + CA_WRC);
    float    (*Zcf)[132] = (float(*)[132])(sm + CA_ZCF);
    uint32_t (*Zcb)[68]  = (uint32_t(*)[68])(sm + CA_ZCB);
    uint32_t (*Gc)[132]  = (uint32_t(*)[132])(sm + CA_GC);

    const int b = blockIdx.x;
    const int tid = threadIdx.x;
    const int lane = tid & 31, wid = tid >> 5;
    const int wm = wid & 3, wn = wid >> 2;
    const int g = lane >> 2, q = lane & 3;

#pragma unroll
    for (int i = 0; i < 8; i++)
        adjs[i * 512 + tid] = g_adj[b * 4096 + i * 512 + tid];

    {
        const int row = tid >> 3;
        const int off = (tid & 7) * 8;
#pragma unroll
        for (int u = 0; u < 2; u++) {
            const int o = off + u * 4;
            float4 v = *(const float4*)(x + (size_t)(b * 64 + row) * 64 + o);
            uint32_t h01, l01, h23, l23;
            split2(v.x, v.y, h01, l01);
            split2(v.z, v.w, h23, l23);
            const int p = o >> 1;
            Xs[row][p]          = h01;
            Xs[row][p + 1]      = h23;
            Xs[row][32 + p]     = l01;
            Xs[row][32 + p + 1] = l23;
        }
    }
    __syncthreads();

    float acc2[2][4] = {};
    const int pc = tid >> 4;
    const int wcolb = (tid & 15) * 8;

#pragma unroll 1
    for (int t = 0; t < 32; t++) {
        const int k0 = 2 * t;
#pragma unroll
        for (int u = 0; u < 2; u++) {
            const int col = wcolb + u * 4;
            const int k = k0 + (col >> 6);
            const int d = col & 63;
            const float* wp = Wagg + ((size_t)k * 64 + 2 * pc) * 64 + d;
            float4 r0 = *(const float4*)(wp);
            float4 r1 = *(const float4*)(wp + 64);
            uint32_t h, l;
            split2(r0.x, r1.x, h, l); Wrc[pc][col]     = h; Wrc[32 + pc][col]     = l;
            split2(r0.y, r1.y, h, l); Wrc[pc][col + 1] = h; Wrc[32 + pc][col + 1] = l;
            split2(r0.z, r1.z, h, l); Wrc[pc][col + 2] = h; Wrc[32 + pc][col + 2] = l;
            split2(r0.w, r1.w, h, l); Wrc[pc][col + 3] = h; Wrc[32 + pc][col + 3] = l;
        }
#pragma unroll
        for (int it = 0; it < 8; it++) {
            const int idx = it * 512 + tid;
            const int i = idx >> 6, j = idx & 63;
            const int e = adjs[idx];
            float v0 = 0.f, v1 = 0.f;
            if (e >= 0) {
                v0 = CoutT[(size_t)k0 * EE + e];
                v1 = CoutT[(size_t)(k0 + 1) * EE + e];
            }
            uint32_t h, l;
            split2(v0, v1, h, l);
            Gc[i][j]      = h;
            Gc[i][64 + j] = l;
        }
        __syncthreads();

        {
            float acc1[4][4] = {};
            const int row = wm * 16 + g;
#pragma unroll
            for (int ks = 0; ks < 4; ks++) {
                uint32_t ah[4], al[4];
                ah[0] = Xs[row][ks * 8 + q];       ah[1] = Xs[row + 8][ks * 8 + q];
                ah[2] = Xs[row][ks * 8 + q + 4];   ah[3] = Xs[row + 8][ks * 8 + q + 4];
                al[0] = Xs[row][32 + ks * 8 + q];     al[1] = Xs[row + 8][32 + ks * 8 + q];
                al[2] = Xs[row][32 + ks * 8 + q + 4]; al[3] = Xs[row + 8][32 + ks * 8 + q + 4];
#pragma unroll
                for (int nt = 0; nt < 4; nt++) {
                    const int col = wn * 32 + nt * 8 + g;
                    uint32_t bh[2] = {Wrc[ks * 8 + q][col], Wrc[ks * 8 + q + 4][col]};
                    uint32_t bl[2] = {Wrc[32 + ks * 8 + q][col], Wrc[32 + ks * 8 + q + 4][col]};
                    mma16(acc1[nt], ah, bh);
                    mma16(acc1[nt], ah, bl);
                    mma16(acc1[nt], al, bh);
                }
            }
#pragma unroll
            for (int nt = 0; nt < 4; nt++) {
                const int col = wn * 32 + nt * 8 + 2 * q;
                *(float2*)(&Zcf[row][col])     = make_float2(acc1[nt][0], acc1[nt][1]);
                *(float2*)(&Zcf[row + 8][col]) = make_float2(acc1[nt][2], acc1[nt][3]);
            }
        }
        __syncthreads();

#pragma unroll
        for (int it = 0; it < 8; it++) {
            const int idx = it * 512 + tid;
            const int j = idx >> 6, d = idx & 63;
            uint32_t h, l;
            split2(Zcf[j][d], Zcf[j][64 + d], h, l);
            Zcb[j][d]      = h;
            Zcb[64 + j][d] = l;
        }
        __syncthreads();

        {
            const int row = wm * 16 + g;
#pragma unroll
            for (int ks = 0; ks < 8; ks++) {
                uint32_t ah[4], al[4];
                ah[0] = Gc[row][ks * 8 + q];       ah[1] = Gc[row + 8][ks * 8 + q];
                ah[2] = Gc[row][ks * 8 + q + 4];   ah[3] = Gc[row + 8][ks * 8 + q + 4];
                al[0] = Gc[row][64 + ks * 8 + q];     al[1] = Gc[row + 8][64 + ks * 8 + q];
                al[2] = Gc[row][64 + ks * 8 + q + 4]; al[3] = Gc[row + 8][64 + ks * 8 + q + 4];
#pragma unroll
                for (int nt = 0; nt < 2; nt++) {
                    const int col = wn * 16 + nt * 8 + g;
                    uint32_t bh[2] = {Zcb[ks * 8 + q][col], Zcb[ks * 8 + q + 4][col]};
                    uint32_t bl[2] = {Zcb[64 + ks * 8 + q][col], Zcb[64 + ks * 8 + q + 4][col]};
                    mma16(acc2[nt], ah, bh);
                    mma16(acc2[nt], ah, bl);
                    mma16(acc2[nt], al, bh);
                }
            }
        }
        __syncthreads();
    }

    {
        const int row = b * 64 + wm * 16 + g;
#pragma unroll
        for (int nt = 0; nt < 2; nt++) {
            const int col = wn * 16 + nt * 8 + 2 * q;
            *(float2*)(agg + (size_t)row * 64 + col) =
                make_float2(acc2[nt][0], acc2[nt][1]);
            *(float2*)(agg + (size_t)(row + 8) * 64 + col) =
                make_float2(acc2[nt][2], acc2[nt][3]);
        }
    }
}

// -------------------- weight fragment packing --------------------
__global__ void k_we1_pack(const float* __restrict__ We1) {
    int idx = blockIdx.x * blockDim.x + threadIdx.x;
    if (idx >= 128 * 256) return;
    int p = idx >> 8, col = idx & 255;
    uint32_t h, l;
    split2(We1[(2 * p) * 256 + col], We1[(2 * p + 1) * 256 + col], h, l);
    g_we1p[idx] = make_uint2(h, l);
}
__global__ void k_we2_pack(const float* __restrict__ We2) {
    int idx = blockIdx.x * blockDim.x + threadIdx.x;
    if (idx >= 128 * 64) return;
    int p = idx >> 6, col = idx & 63;
    uint32_t h, l;
    split2(We2[(2 * p) * 64 + col], We2[(2 * p + 1) * 64 + col], h, l);
    g_we2p[idx] = make_uint2(h, l);
}
__global__ void k_pack_w(const float* __restrict__ W1, const float* __restrict__ W2,
                         const float* __restrict__ W3, const float* __restrict__ W4) {
    int idx = blockIdx.x * blockDim.x + threadIdx.x;
    if (idx >= 64 * 256) return;
    int k = idx >> 8, n = idx & 255;
    int sel = n >> 6, col = n & 63;
    const float* W = (sel == 0) ? W1 : (sel == 1) ? W2 : (sel == 2) ? W3 : W4;
    g_wcat[idx] = W[k * 64 + col];
}

// -------------------- adjacency --------------------
__global__ void k_adj_init() {
    int i = blockIdx.x * blockDim.x + threadIdx.x;
    if (i < BB * NL * NL) g_adj[i] = -1;
}
__global__ void k_adj_fill(const int* __restrict__ EI) {
    int e = blockIdx.x * blockDim.x + threadIdx.x;
    if (e >= EE) return;
    int base = EI[e];
    int li = EI[EE + e] - base;
    int lj = EI[2 * EE + e] - base;
    int b = base >> 6;
    g_adj[b * (NL * NL) + li * NL + lj] = e;
}

// -------------------- tmp_mm via out-edge compaction --------------------
__global__ void __launch_bounds__(256) k_mm3() {
    __shared__ int   rowstage[64];
    __shared__ int   kk[16];
    __shared__ int   eo[16];
    __shared__ int   adjs[16][17];
    __shared__ float Xs[16][65];
    const int n = blockIdx.x;
    const int b = n >> 6, li = n & 63;
    const int tid = threadIdx.x;
    const int q = tid >> 6, c = tid & 63;
    const int* badj = g_adj + b * (NL * NL);

    if (tid < 64) rowstage[tid] = badj[li * 64 + tid];
    __syncthreads();
    if (tid == 0) {
        int cnt = 0;
        for (int j = 0; j < 64 && cnt < 16; j++) {
            int e = rowstage[j];
            if (e >= 0) { kk[cnt] = j; eo[cnt] = e; cnt++; }
        }
        for (; cnt < 16; cnt++) { kk[cnt] = -1; eo[cnt] = -1; }
    }
    __syncthreads();
    {
        const int a = tid >> 4, s = tid & 15;
        const int ka = kk[a], ks = kk[s];
        adjs[a][s] = (ka >= 0 && ks >= 0) ? badj[ka * 64 + ks] : -1;
    }
#pragma unroll
    for (int i = 0; i < 4; i++) {
        const int a = q * 4 + i;
        const int e1 = eo[a];
        Xs[a][c] = (e1 >= 0) ? g_e1[(size_t)e1 * 256 + 128 + c] : 0.0f;
    }
    __syncthreads();
#pragma unroll 1
    for (int i = 0; i < 4; i++) {
        const int s = q * 4 + i;
        const int e_out = eo[s];
        if (e_out < 0) continue;
        float acc = 0.0f;
#pragma unroll
        for (int a = 0; a < 16; a++) {
            const int e2 = adjs[a][s];
            if (e2 >= 0) acc += Xs[a][c] * g_e1[(size_t)e2 * 256 + 192 + c];
        }
        g_mm[(size_t)e_out * 64 + c] = acc;
    }
}

// -------------------- LayerNorm(256) + GELU, in-place (node MLP) --------------------
__global__ void k_ln_gelu(float* __restrict__ data,
                          const float* __restrict__ gam,
                          const float* __restrict__ bet) {
    __shared__ float red[8];
    __shared__ float stat[2];
    size_t row = blockIdx.x;
    int t = threadIdx.x;
    float v = data[row * 256 + t];

    float s = v;
#pragma unroll
    for (int o = 16; o > 0; o >>= 1) s += __shfl_down_sync(0xffffffffu, s, o);
    if ((t & 31) == 0) red[t >> 5] = s;
    __syncthreads();
    if (t == 0) {
        float tt = 0.f;
        for (int i = 0; i < 8; i++) tt += red[i];
        stat[0] = tt * (1.0f / 256.0f);
    }
    __syncthreads();
    float mu = stat[0];
    float dv = v - mu;
    float s2 = dv * dv;
#pragma unroll
    for (int o = 16; o > 0; o >>= 1) s2 += __shfl_down_sync(0xffffffffu, s2, o);
    __syncthreads();
    if ((t & 31) == 0) red[t >> 5] = s2;
    __syncthreads();
    if (t == 0) {
        float tt = 0.f;
        for (int i = 0; i < 8; i++) tt += red[i];
        stat[1] = rsqrtf(tt * (1.0f / 256.0f) + 1e-5f);
    }
    __syncthreads();
    float y = dv * stat[1] * gam[t] + bet[t];
    float out = 0.5f * y * (1.0f + erff(y * 0.70710678118654752440f));
    data[row * 256 + t] = out;
}

// -------------------- launch --------------------
static inline void gemm(const float* A, const float* B, float* C, int M, int N, int K) {
    if (N % 128 == 0) {
        dim3 grd(M / 128, N / 128);
        k_gemm_f16<128><<<grd, 256>>>(A, B, C, M, N, K);
    } else {
        dim3 grd(M / 128, N / 64);
        k_gemm_f16<64><<<grd, 256>>>(A, B, C, M, N, K);
    }
}

extern "C" void kernel_launch(void* const* d_in, const int* in_sizes, int n_in,
                              void* d_out, int out_size) {
    const float* x    = (const float*)d_in[0];
    const float* Cin  = (const float*)d_in[1];
    const float* W1   = (const float*)d_in[2];
    const float* W2   = (const float*)d_in[3];
    const float* W3   = (const float*)d_in[4];
    const float* W4   = (const float*)d_in[5];
    const float* W5   = (const float*)d_in[6];
    const float* We1  = (const float*)d_in[7];
    const float* lneg = (const float*)d_in[8];
    const float* lneb = (const float*)d_in[9];
    const float* We2  = (const float*)d_in[10];
    const float* Wn1  = (const float*)d_in[11];
    const float* lnng = (const float*)d_in[12];
    const float* lnnb = (const float*)d_in[13];
    const float* Wn2  = (const float*)d_in[14];
    const float* Wagg = (const float*)d_in[15];
    const int*   EI   = (const int*)d_in[16];

    float* xout = (float*)d_out;
    float* Cout = (float*)d_out + (size_t)NN * 64;

    cudaFuncSetAttribute(k_edge_mlp, cudaFuncAttributeMaxDynamicSharedMemorySize, SMEM_EDGE);
    cudaFuncSetAttribute(k_cagg, cudaFuncAttributeMaxDynamicSharedMemorySize, SMEM_CAGG);

    float *p_h5, *p_e1, *p_mm, *p_ct, *p_agg, *p_n1, *p_wcat;
    uint2 *p_we1p, *p_we2p;
    cudaGetSymbolAddress((void**)&p_h5, g_h5);
    cudaGetSymbolAddress((void**)&p_e1, g_e1);
    cudaGetSymbolAddress((void**)&p_mm, g_mm);
    cudaGetSymbolAddress((void**)&p_ct, g_ct);
    cudaGetSymbolAddress((void**)&p_agg, g_agg);
    cudaGetSymbolAddress((void**)&p_n1, g_n1);
    cudaGetSymbolAddress((void**)&p_wcat, g_wcat);
    cudaGetSymbolAddress((void**)&p_we1p, g_we1p);
    cudaGetSymbolAddress((void**)&p_we2p, g_we2p);

    // prep
    k_pack_w<<<(64 * 256 + 255) / 256, 256>>>(W1, W2, W3, W4);
    k_we1_pack<<<(128 * 256 + 255) / 256, 256>>>(We1);
    k_we2_pack<<<(128 * 64 + 255) / 256, 256>>>(We2);
    k_adj_init<<<(BB * NL * NL + 255) / 256, 256>>>();
    k_adj_fill<<<(EE + 255) / 256, 256>>>(EI);

    // pre-GEMMs
    gemm(x,   W5,     p_h5, NN, 64, 64);
    gemm(Cin, p_wcat, p_e1, EE, 256, 64);   // [t1|t2|X3|Y4]

    // tmp_mm
    k_mm3<<<NN, 256>>>();

    // fused edge MLP
    k_edge_mlp<<<EE / 128, 512, SMEM_EDGE>>>(Cin, p_e1, p_h5, p_mm, EI,
                                             p_we1p, p_we2p, Cout, p_ct, lneg, lneb);

    // fused Conv_agg
    k_cagg<<<BB, 512, SMEM_CAGG>>>(x, Wagg, p_ct, p_agg);

    // node MLP
    gemm(p_agg, Wn1, p_n1, NN, 256, 64);
    k_ln_gelu<<<NN, 256>>>(p_n1, lnng, lnnb);
    gemm(p_n1, Wn2, xout, NN, 64, 256);
}

// round 15
// speedup vs baseline: 1.0728x; 1.0728x over previous
#include <cuda_runtime.h>
#include <cuda_fp16.h>
#include <cstdint>
#include <cstddef>

#define BB 128
#define NL 64
#define EE 131072
#define NN 8192
#define KD 4096

// -------------------- device scratch --------------------
__device__ float g_h5 [NN * 64];
__device__ float g_e1 [EE * 256];      // cat[t1|t2|X3|Y4]
__device__ float g_mm [EE * 64];       // tmp_mm result
__device__ float g_ct [64 * EE];       // CoutT
__device__ float g_agg[NN * 64];
__device__ float g_wcat[64 * 256];     // [W1|W2|W3|W4]
__device__ uint2 g_we1p[128 * 256];    // We1 split pairs [k-pair][col]
__device__ uint2 g_we2p[128 * 64];
__device__ uint2 g_wn1p[32 * 256];
__device__ uint2 g_wn2p[128 * 64];
__device__ int   g_adj[BB * NL * NL];

// -------------------- mma helpers --------------------
__device__ __forceinline__ void mma16(float* c, const uint32_t* a, const uint32_t* b) {
    asm volatile(
        "mma.sync.aligned.m16n8k16.row.col.f32.f16.f16.f32 "
        "{%0,%1,%2,%3}, {%4,%5,%6,%7}, {%8,%9}, {%0,%1,%2,%3};"
        : "+f"(c[0]), "+f"(c[1]), "+f"(c[2]), "+f"(c[3])
        : "r"(a[0]), "r"(a[1]), "r"(a[2]), "r"(a[3]), "r"(b[0]), "r"(b[1]));
}
__device__ __forceinline__ void split2(float x, float y, uint32_t& h, uint32_t& l) {
    __half2 hh = __floats2half2_rn(x, y);
    float2 hf = __half22float2(hh);
    __half2 ll = __floats2half2_rn(x - hf.x, y - hf.y);
    h = *(uint32_t*)&hh;
    l = *(uint32_t*)&ll;
}

// ==================== split-FP16 3-term mma.sync GEMM (standalone) ====================
#define APAD2 36

template<int NT>
__global__ void __launch_bounds__(256, 2) k_gemm_f16(const float* __restrict__ A,
                                                     const float* __restrict__ B,
                                                     float* __restrict__ C,
                                                     int M, int N, int K) {
    constexpr int BPAD2 = (NT == 64) ? 72 : 136;
    constexpr int NTW = NT / 16;
    __shared__ uint32_t As2[128][APAD2];
    __shared__ uint32_t Bs2[32][BPAD2];
    const int tid = threadIdx.x;
    const int lane = tid & 31, wid = tid >> 5;
    const int wm = wid & 3, wn = wid >> 2;
    const int g = lane >> 2, q = lane & 3;
    const int m0 = blockIdx.x * 128, n0 = blockIdx.y * NT;

    const int ar = tid >> 3;
    const int ac = (tid & 7) * 4;
    const int ap = ac >> 1;
    constexpr int BTPR = NT / 4;
    const int bp = tid / BTPR;
    const int bn = (tid % BTPR) * 4;

    float acc[2][NTW][4] = {};

    for (int k0 = 0; k0 < K; k0 += 32) {
#pragma unroll
        for (int i = 0; i < 4; i++) {
            const int row = ar + i * 32;
            float4 v = *(const float4*)(A + (size_t)(m0 + row) * K + k0 + ac);
            uint32_t h01, l01, h23, l23;
            split2(v.x, v.y, h01, l01);
            split2(v.z, v.w, h23, l23);
            As2[row][ap]      = h01;
            As2[row][ap + 1]  = h23;
            As2[row][ap + 16] = l01;
            As2[row][ap + 17] = l23;
        }
#pragma unroll
        for (int it = 0; it < NT / 64; it++) {
            const int p = bp + it * 8;
            const float* r0p = B + (size_t)(k0 + 2 * p) * N + n0 + bn;
            float4 r0 = *(const float4*)(r0p);
            float4 r1 = *(const float4*)(r0p + N);
            uint32_t h, l;
            split2(r0.x, r1.x, h, l); Bs2[p][bn]     = h; Bs2[p + 16][bn]     = l;
            split2(r0.y, r1.y, h, l); Bs2[p][bn + 1] = h; Bs2[p + 16][bn + 1] = l;
            split2(r0.z, r1.z, h, l); Bs2[p][bn + 2] = h; Bs2[p + 16][bn + 2] = l;
            split2(r0.w, r1.w, h, l); Bs2[p][bn + 3] = h; Bs2[p + 16][bn + 3] = l;
        }
        __syncthreads();

#pragma unroll
        for (int s = 0; s < 2; s++) {
            uint32_t ah[2][4], al[2][4];
#pragma unroll
            for (int mt = 0; mt < 2; mt++) {
                const int row = wm * 32 + mt * 16 + g;
                ah[mt][0] = As2[row][s * 8 + q];
                ah[mt][1] = As2[row + 8][s * 8 + q];
                ah[mt][2] = As2[row][s * 8 + q + 4];
                ah[mt][3] = As2[row + 8][s * 8 + q + 4];
                al[mt][0] = As2[row][16 + s * 8 + q];
                al[mt][1] = As2[row + 8][16 + s * 8 + q];
                al[mt][2] = As2[row][16 + s * 8 + q + 4];
                al[mt][3] = As2[row + 8][16 + s * 8 + q + 4];
            }
#pragma unroll
            for (int nt = 0; nt < NTW; nt++) {
                const int col = wn * (NT / 2) + nt * 8 + g;
                uint32_t bh[2], bl[2];
                bh[0] = Bs2[s * 8 + q][col];
                bh[1] = Bs2[s * 8 + q + 4][col];
                bl[0] = Bs2[16 + s * 8 + q][col];
                bl[1] = Bs2[16 + s * 8 + q + 4][col];
#pragma unroll
                for (int mt = 0; mt < 2; mt++) {
                    mma16(acc[mt][nt], ah[mt], bh);
                    mma16(acc[mt][nt], ah[mt], bl);
                    mma16(acc[mt][nt], al[mt], bh);
                }
            }
        }
        __syncthreads();
    }

#pragma unroll
    for (int mt = 0; mt < 2; mt++) {
        const int row = m0 + wm * 32 + mt * 16 + g;
#pragma unroll
        for (int nt = 0; nt < NTW; nt++) {
            const int col = n0 + wn * (NT / 2) + nt * 8 + q * 2;
            *(float2*)(C + (size_t)row * N + col) =
                make_float2(acc[mt][nt][0], acc[mt][nt][1]);
            *(float2*)(C + (size_t)(row + 8) * N + col) =
                make_float2(acc[mt][nt][2], acc[mt][nt][3]);
        }
    }
}

// ==================== fused edge MLP, 512 thr (R13 base; B copied pre-split) ========
#define HIDS 264
#define BW1  264
#define SM_AS2 0
#define SM_BS2 4608
#define SM_HID (SM_BS2 + 32 * BW1)
#define SM_RST (SM_HID + 128 * HIDS)
#define SM_GB  (SM_RST + 256)
#define SM_EDGE_WORDS (SM_GB + 512)
#define SMEM_EDGE (SM_EDGE_WORDS * 4)
#define TS 132

__global__ void __launch_bounds__(512) k_edge_mlp(const float* __restrict__ Cin,
                                                  const float* __restrict__ cat,
                                                  const float* __restrict__ h5,
                                                  const float* __restrict__ mm,
                                                  const int* __restrict__ EI,
                                                  const uint2* __restrict__ B1,
                                                  const uint2* __restrict__ B2,
                                                  float* __restrict__ Cout,
                                                  float* __restrict__ CoutT,
                                                  const float* __restrict__ gam,
                                                  const float* __restrict__ bet) {
    extern __shared__ uint32_t sm[];
    uint32_t (*As2)[36]  = (uint32_t(*)[36])(sm + SM_AS2);
    uint32_t (*Bs2)[BW1] = (uint32_t(*)[BW1])(sm + SM_BS2);
    uint32_t* hidw = sm + SM_HID;
    float*    hidf = (float*)hidw;
    float*    rstat = (float*)(sm + SM_RST);
    float*    gb    = (float*)(sm + SM_GB);

    const int tid = threadIdx.x;
    const int lane = tid & 31, wid = tid >> 5;   // 16 warps
    const int wm = wid & 3, wn = wid >> 2;       // 4 x 4
    const int g = lane >> 2, q = lane & 3;
    const int m0 = blockIdx.x * 128;

    if (tid < 256) {
        gb[2 * tid]     = gam[tid];
        gb[2 * tid + 1] = bet[tid];
    }

    const int ar = tid >> 2;            // 0..127
    const int ac = (tid & 3) * 8;       // 0,8,16,24
    const int ap = ac >> 1;             // 0,4,8,12
    const int bp = tid >> 5;            // 0..15
    const int bn = (tid & 31) * 8;      // 0..248

    int sl;
    {
        const int e = m0 + ar;
        const int s = EI[EE + e], d = EI[2 * EE + e];
        sl = (s == d) ? s : -1;
    }

    // ---------------- GEMM1: hidden = tmp @ We1, single pass, N=256 ----------------
    float acc[2][8][4] = {};
#pragma unroll 1
    for (int c = 0; c < 8; c++) {
        const int k0 = c * 32;
        {   // A synthesis + split
            const size_t e = (size_t)(m0 + ar);
            float4 v0, v1;
            if (c < 2) {
                const float* p = Cin + e * 64 + k0 + ac;
                v0 = *(const float4*)(p);
                v1 = *(const float4*)(p + 4);
            } else if (c < 4) {
                const float* p1 = cat + e * 256 + (k0 - 64) + ac;
                const float* p2 = p1 + 64;
                float4 a0 = *(const float4*)(p1);
                float4 a1 = *(const float4*)(p1 + 4);
                float4 b0 = *(const float4*)(p2);
                float4 b1 = *(const float4*)(p2 + 4);
                v0 = make_float4(a0.x * b0.x, a0.y * b0.y, a0.z * b0.z, a0.w * b0.w);
                v1 = make_float4(a1.x * b1.x, a1.y * b1.y, a1.z * b1.z, a1.w * b1.w);
            } else if (c < 6) {
                if (sl >= 0) {
                    const float* p = h5 + (size_t)sl * 64 + (k0 - 128) + ac;
                    v0 = *(const float4*)(p);
                    v1 = *(const float4*)(p + 4);
                } else {
                    v0 = make_float4(0.f, 0.f, 0.f, 0.f);
                    v1 = v0;
                }
            } else {
                const float* p = mm + e * 64 + (k0 - 192) + ac;
                v0 = *(const float4*)(p);
                v1 = *(const float4*)(p + 4);
            }
            uint32_t h, l;
            split2(v0.x, v0.y, h, l); As2[ar][ap]      = h; As2[ar][ap + 16] = l;
            split2(v0.z, v0.w, h, l); As2[ar][ap + 1]  = h; As2[ar][ap + 17] = l;
            split2(v1.x, v1.y, h, l); As2[ar][ap + 2]  = h; As2[ar][ap + 18] = l;
            split2(v1.z, v1.w, h, l); As2[ar][ap + 3]  = h; As2[ar][ap + 19] = l;
        }
        {   // B staging: copy pre-split pairs (no cvt ALU)
            const uint2* src = B1 + (size_t)(c * 16 + bp) * 256 + bn;
            uint4 w0 = *(const uint4*)(src);
            uint4 w1 = *(const uint4*)(src + 2);
            uint4 w2 = *(const uint4*)(src + 4);
            uint4 w3 = *(const uint4*)(src + 6);
            *(uint4*)&Bs2[bp][bn]          = make_uint4(w0.x, w0.z, w1.x, w1.z);
            *(uint4*)&Bs2[bp + 16][bn]     = make_uint4(w0.y, w0.w, w1.y, w1.w);
            *(uint4*)&Bs2[bp][bn + 4]      = make_uint4(w2.x, w2.z, w3.x, w3.z);
            *(uint4*)&Bs2[bp + 16][bn + 4] = make_uint4(w2.y, w2.w, w3.y, w3.w);
        }
        __syncthreads();
#pragma unroll
        for (int s = 0; s < 2; s++) {
            uint32_t ah[2][4], al[2][4];
#pragma unroll
            for (int mt = 0; mt < 2; mt++) {
                const int row = wm * 32 + mt * 16 + g;
                ah[mt][0] = As2[row][s * 8 + q];
                ah[mt][1] = As2[row + 8][s * 8 + q];
                ah[mt][2] = As2[row][s * 8 + q + 4];
                ah[mt][3] = As2[row + 8][s * 8 + q + 4];
                al[mt][0] = As2[row][16 + s * 8 + q];
                al[mt][1] = As2[row + 8][16 + s * 8 + q];
                al[mt][2] = As2[row][16 + s * 8 + q + 4];
                al[mt][3] = As2[row + 8][16 + s * 8 + q + 4];
            }
#pragma unroll
            for (int nt = 0; nt < 8; nt++) {
                const int col = wn * 64 + nt * 8 + g;
                uint32_t bh[2], bl[2];
                bh[0] = Bs2[s * 8 + q][col];
                bh[1] = Bs2[s * 8 + q + 4][col];
                bl[0] = Bs2[16 + s * 8 + q][col];
                bl[1] = Bs2[16 + s * 8 + q + 4][col];
#pragma unroll
                for (int mt = 0; mt < 2; mt++) {
                    mma16(acc[mt][nt], ah[mt], bh);
                    mma16(acc[mt][nt], ah[mt], bl);
                    mma16(acc[mt][nt], al[mt], bh);
                }
            }
        }
        __syncthreads();
    }
    // park raw hidden
#pragma unroll
    for (int mt = 0; mt < 2; mt++) {
        const int row = wm * 32 + mt * 16 + g;
#pragma unroll
        for (int nt = 0; nt < 8; nt++) {
            const int col = wn * 64 + nt * 8 + 2 * q;
            *(float2*)(hidf + (size_t)row * HIDS + col) =
                make_float2(acc[mt][nt][0], acc[mt][nt][1]);
            *(float2*)(hidf + (size_t)(row + 8) * HIDS + col) =
                make_float2(acc[mt][nt][2], acc[mt][nt][3]);
        }
    }
    __syncthreads();

    // ---------------- LN stats ----------------
#pragma unroll 1
    for (int rr = 0; rr < 8; rr++) {
        const int row = wid * 8 + rr;
        float s1 = 0.f, s2 = 0.f;
#pragma unroll
        for (int j = 0; j < 8; j++) {
            float v = hidf[(size_t)row * HIDS + lane + 32 * j];
            s1 += v; s2 += v * v;
        }
#pragma unroll
        for (int o = 16; o > 0; o >>= 1) {
            s1 += __shfl_xor_sync(0xffffffffu, s1, o);
            s2 += __shfl_xor_sync(0xffffffffu, s2, o);
        }
        if (lane == 0) {
            float mu = s1 * (1.0f / 256.0f);
            float var = fmaxf(s2 * (1.0f / 256.0f) - mu * mu, 0.f);
            rstat[2 * row]     = mu;
            rstat[2 * row + 1] = rsqrtf(var + 1e-5f);
        }
    }
    __syncthreads();

    // ---------------- LN + GELU + split-pack, in place ----------------
#pragma unroll 1
    for (int i = 0; i < 32; i++) {
        const int idx = i * 512 + tid;
        const int r = idx >> 7, p = idx & 127;
        float2 v = *(float2*)(hidf + (size_t)r * HIDS + 2 * p);
        const float mu = rstat[2 * r], rs = rstat[2 * r + 1];
        float4 gbv = *(float4*)(gb + 4 * p);
        float y0 = (v.x - mu) * rs * gbv.x + gbv.y;
        float y1 = (v.y - mu) * rs * gbv.z + gbv.w;
        y0 = 0.5f * y0 * (1.0f + erff(y0 * 0.70710678118654752440f));
        y1 = 0.5f * y1 * (1.0f + erff(y1 * 0.70710678118654752440f));
        uint32_t h, l;
        split2(y0, y1, h, l);
        hidw[(size_t)r * HIDS + 2 * p]     = h;
        hidw[(size_t)r * HIDS + 2 * p + 1] = l;
    }
    __syncthreads();

    // ---------------- GEMM2: Cout = hidden @ We2 ----------------
    float acc2[2][2][4] = {};
#pragma unroll 1
    for (int s = 0; s < 16; s++) {
        uint32_t ah[2][4], al[2][4];
#pragma unroll
        for (int mt = 0; mt < 2; mt++) {
            const int row = wm * 32 + mt * 16 + g;
            uint2 t0 = *(uint2*)(hidw + (size_t)row * HIDS + 16 * s + 2 * q);
            uint2 t1 = *(uint2*)(hidw + (size_t)(row + 8) * HIDS + 16 * s + 2 * q);
            uint2 t2 = *(uint2*)(hidw + (size_t)row * HIDS + 16 * s + 2 * q + 8);
            uint2 t3 = *(uint2*)(hidw + (size_t)(row + 8) * HIDS + 16 * s + 2 * q + 8);
            ah[mt][0] = t0.x; al[mt][0] = t0.y;
            ah[mt][1] = t1.x; al[mt][1] = t1.y;
            ah[mt][2] = t2.x; al[mt][2] = t2.y;
            ah[mt][3] = t3.x; al[mt][3] = t3.y;
        }
#pragma unroll
        for (int nt = 0; nt < 2; nt++) {
            const int col = wn * 16 + nt * 8 + g;
            uint2 u0 = __ldg(&B2[(8 * s + q) * 64 + col]);
            uint2 u1 = __ldg(&B2[(8 * s + q + 4) * 64 + col]);
            uint32_t bh[2] = {u0.x, u1.x};
            uint32_t bl[2] = {u0.y, u1.y};
#pragma unroll
            for (int mt = 0; mt < 2; mt++) {
                mma16(acc2[mt][nt], ah[mt], bh);
                mma16(acc2[mt][nt], ah[mt], bl);
                mma16(acc2[mt][nt], al[mt], bh);
            }
        }
    }
    __syncthreads();

    float* T = (float*)(sm + SM_HID);
#pragma unroll
    for (int mt = 0; mt < 2; mt++) {
        const int rloc = wm * 32 + mt * 16 + g;
        const int row = m0 + rloc;
#pragma unroll
        for (int nt = 0; nt < 2; nt++) {
            const int col = wn * 16 + nt * 8 + 2 * q;
            *(float2*)(Cout + (size_t)row * 64 + col) =
                make_float2(acc2[mt][nt][0], acc2[mt][nt][1]);
            *(float2*)(Cout + (size_t)(row + 8) * 64 + col) =
                make_float2(acc2[mt][nt][2], acc2[mt][nt][3]);
            T[col * TS + rloc]           = acc2[mt][nt][0];
            T[(col + 1) * TS + rloc]     = acc2[mt][nt][1];
            T[col * TS + rloc + 8]       = acc2[mt][nt][2];
            T[(col + 1) * TS + rloc + 8] = acc2[mt][nt][3];
        }
    }
    __syncthreads();
#pragma unroll
    for (int i = 0; i < 16; i++) {
        const int idx = i * 512 + tid;
        const int k = idx >> 7, r = idx & 127;
        CoutT[(size_t)k * EE + m0 + r] = T[k * TS + r];
    }
}

// ==================== fused node MLP, 512 thr ====================
// xout = GELU(LN(agg @ Wn1)) @ Wn2, per 128 rows. Same skeleton as edge MLP.
__global__ void __launch_bounds__(512) k_node_mlp(const float* __restrict__ A,
                                                  const uint2* __restrict__ B1,
                                                  const uint2* __restrict__ B2,
                                                  float* __restrict__ xout,
                                                  const float* __restrict__ gam,
                                                  const float* __restrict__ bet) {
    extern __shared__ uint32_t sm[];
    uint32_t (*As2)[36]  = (uint32_t(*)[36])(sm + SM_AS2);
    uint32_t (*Bs2)[BW1] = (uint32_t(*)[BW1])(sm + SM_BS2);
    uint32_t* hidw = sm + SM_HID;
    float*    hidf = (float*)hidw;
    float*    rstat = (float*)(sm + SM_RST);
    float*    gb    = (float*)(sm + SM_GB);

    const int tid = threadIdx.x;
    const int lane = tid & 31, wid = tid >> 5;
    const int wm = wid & 3, wn = wid >> 2;
    const int g = lane >> 2, q = lane & 3;
    const int m0 = blockIdx.x * 128;

    if (tid < 256) {
        gb[2 * tid]     = gam[tid];
        gb[2 * tid + 1] = bet[tid];
    }

    const int ar = tid >> 2;
    const int ac = (tid & 3) * 8;
    const int ap = ac >> 1;
    const int bp = tid >> 5;
    const int bn = (tid & 31) * 8;

    // ---------------- GEMM1: hid = agg @ Wn1 (K=64: 2 chunks) ----------------
    float acc[2][8][4] = {};
#pragma unroll 1
    for (int c = 0; c < 2; c++) {
        const int k0 = c * 32;
        {
            const float* p = A + (size_t)(m0 + ar) * 64 + k0 + ac;
            float4 v0 = *(const float4*)(p);
            float4 v1 = *(const float4*)(p + 4);
            uint32_t h, l;
            split2(v0.x, v0.y, h, l); As2[ar][ap]      = h; As2[ar][ap + 16] = l;
            split2(v0.z, v0.w, h, l); As2[ar][ap + 1]  = h; As2[ar][ap + 17] = l;
            split2(v1.x, v1.y, h, l); As2[ar][ap + 2]  = h; As2[ar][ap + 18] = l;
            split2(v1.z, v1.w, h, l); As2[ar][ap + 3]  = h; As2[ar][ap + 19] = l;
        }
        {
            const uint2* src = B1 + (size_t)(c * 16 + bp) * 256 + bn;
            uint4 w0 = *(const uint4*)(src);
            uint4 w1 = *(const uint4*)(src + 2);
            uint4 w2 = *(const uint4*)(src + 4);
            uint4 w3 = *(const uint4*)(src + 6);
            *(uint4*)&Bs2[bp][bn]          = make_uint4(w0.x, w0.z, w1.x, w1.z);
            *(uint4*)&Bs2[bp + 16][bn]     = make_uint4(w0.y, w0.w, w1.y, w1.w);
            *(uint4*)&Bs2[bp][bn + 4]      = make_uint4(w2.x, w2.z, w3.x, w3.z);
            *(uint4*)&Bs2[bp + 16][bn + 4] = make_uint4(w2.y, w2.w, w3.y, w3.w);
        }
        __syncthreads();
#pragma unroll
        for (int s = 0; s < 2; s++) {
            uint32_t ah[2][4], al[2][4];
#pragma unroll
            for (int mt = 0; mt < 2; mt++) {
                const int row = wm * 32 + mt * 16 + g;
                ah[mt][0] = As2[row][s * 8 + q];
                ah[mt][1] = As2[row + 8][s * 8 + q];
                ah[mt][2] = As2[row][s * 8 + q + 4];
                ah[mt][3] = As2[row + 8][s * 8 + q + 4];
                al[mt][0] = As2[row][16 + s * 8 + q];
                al[mt][1] = As2[row + 8][16 + s * 8 + q];
                al[mt][2] = As2[row][16 + s * 8 + q + 4];
                al[mt][3] = As2[row + 8][16 + s * 8 + q + 4];
            }
#pragma unroll
            for (int nt = 0; nt < 8; nt++) {
                const int col = wn * 64 + nt * 8 + g;
                uint32_t bh[2], bl[2];
                bh[0] = Bs2[s * 8 + q][col];
                bh[1] = Bs2[s * 8 + q + 4][col];
                bl[0] = Bs2[16 + s * 8 + q][col];
                bl[1] = Bs2[16 + s * 8 + q + 4][col];
#pragma unroll
                for (int mt = 0; mt < 2; mt++) {
                    mma16(acc[mt][nt], ah[mt], bh);
                    mma16(acc[mt][nt], ah[mt], bl);
                    mma16(acc[mt][nt], al[mt], bh);
                }
            }
        }
        __syncthreads();
    }
#pragma unroll
    for (int mt = 0; mt < 2; mt++) {
        const int row = wm * 32 + mt * 16 + g;
#pragma unroll
        for (int nt = 0; nt < 8; nt++) {
            const int col = wn * 64 + nt * 8 + 2 * q;
            *(float2*)(hidf + (size_t)row * HIDS + col) =
                make_float2(acc[mt][nt][0], acc[mt][nt][1]);
            *(float2*)(hidf + (size_t)(row + 8) * HIDS + col) =
                make_float2(acc[mt][nt][2], acc[mt][nt][3]);
        }
    }
    __syncthreads();

    // ---------------- LN stats ----------------
#pragma unroll 1
    for (int rr = 0; rr < 8; rr++) {
        const int row = wid * 8 + rr;
        float s1 = 0.f, s2 = 0.f;
#pragma unroll
        for (int j = 0; j < 8; j++) {
            float v = hidf[(size_t)row * HIDS + lane + 32 * j];
            s1 += v; s2 += v * v;
        }
#pragma unroll
        for (int o = 16; o > 0; o >>= 1) {
            s1 += __shfl_xor_sync(0xffffffffu, s1, o);
            s2 += __shfl_xor_sync(0xffffffffu, s2, o);
        }
        if (lane == 0) {
            float mu = s1 * (1.0f / 256.0f);
            float var = fmaxf(s2 * (1.0f / 256.0f) - mu * mu, 0.f);
            rstat[2 * row]     = mu;
            rstat[2 * row + 1] = rsqrtf(var + 1e-5f);
        }
    }
    __syncthreads();

    // ---------------- LN + GELU + split-pack ----------------
#pragma unroll 1
    for (int i = 0; i < 32; i++) {
        const int idx = i * 512 + tid;
        const int r = idx >> 7, p = idx & 127;
        float2 v = *(float2*)(hidf + (size_t)r * HIDS + 2 * p);
        const float mu = rstat[2 * r], rs = rstat[2 * r + 1];
        float4 gbv = *(float4*)(gb + 4 * p);
        float y0 = (v.x - mu) * rs * gbv.x + gbv.y;
        float y1 = (v.y - mu) * rs * gbv.z + gbv.w;
        y0 = 0.5f * y0 * (1.0f + erff(y0 * 0.70710678118654752440f));
        y1 = 0.5f * y1 * (1.0f + erff(y1 * 0.70710678118654752440f));
        uint32_t h, l;
        split2(y0, y1, h, l);
        hidw[(size_t)r * HIDS + 2 * p]     = h;
        hidw[(size_t)r * HIDS + 2 * p + 1] = l;
    }
    __syncthreads();

    // ---------------- GEMM2: xout = hid @ Wn2 ----------------
    float acc2[2][2][4] = {};
#pragma unroll 1
    for (int s = 0; s < 16; s++) {
        uint32_t ah[2][4], al[2][4];
#pragma unroll
        for (int mt = 0; mt < 2; mt++) {
            const int row = wm * 32 + mt * 16 + g;
            uint2 t0 = *(uint2*)(hidw + (size_t)row * HIDS + 16 * s + 2 * q);
            uint2 t1 = *(uint2*)(hidw + (size_t)(row + 8) * HIDS + 16 * s + 2 * q);
            uint2 t2 = *(uint2*)(hidw + (size_t)row * HIDS + 16 * s + 2 * q + 8);
            uint2 t3 = *(uint2*)(hidw + (size_t)(row + 8) * HIDS + 16 * s + 2 * q + 8);
            ah[mt][0] = t0.x; al[mt][0] = t0.y;
            ah[mt][1] = t1.x; al[mt][1] = t1.y;
            ah[mt][2] = t2.x; al[mt][2] = t2.y;
            ah[mt][3] = t3.x; al[mt][3] = t3.y;
        }
#pragma unroll
        for (int nt = 0; nt < 2; nt++) {
            const int col = wn * 16 + nt * 8 + g;
            uint2 u0 = __ldg(&B2[(8 * s + q) * 64 + col]);
            uint2 u1 = __ldg(&B2[(8 * s + q + 4) * 64 + col]);
            uint32_t bh[2] = {u0.x, u1.x};
            uint32_t bl[2] = {u0.y, u1.y};
#pragma unroll
            for (int mt = 0; mt < 2; mt++) {
                mma16(acc2[mt][nt], ah[mt], bh);
                mma16(acc2[mt][nt], ah[mt], bl);
                mma16(acc2[mt][nt], al[mt], bh);
            }
        }
    }
#pragma unroll
    for (int mt = 0; mt < 2; mt++) {
        const int row = m0 + wm * 32 + mt * 16 + g;
#pragma unroll
        for (int nt = 0; nt < 2; nt++) {
            const int col = wn * 16 + nt * 8 + 2 * q;
            *(float2*)(xout + (size_t)row * 64 + col) =
                make_float2(acc2[mt][nt][0], acc2[mt][nt][1]);
            *(float2*)(xout + (size_t)(row + 8) * 64 + col) =
                make_float2(acc2[mt][nt][2], acc2[mt][nt][3]);
        }
    }
}

// ==================== fused Conv_agg, 512 threads ==========
#define CA_ADJ 0
#define CA_XS  4096
#define CA_WRC 8448
#define CA_ZCF 16896
#define CA_ZCB 25344
#define CA_GC  34048
#define CA_WORDS 42496
#define SMEM_CAGG (CA_WORDS * 4)

__global__ void __launch_bounds__(512) k_cagg(const float* __restrict__ x,
                                              const float* __restrict__ Wagg,
                                              const float* __restrict__ CoutT,
                                              float* __restrict__ agg) {
    extern __shared__ uint32_t sm[];
    int* adjs = (int*)(sm + CA_ADJ);
    uint32_t (*Xs)[68]   = (uint32_t(*)[68])(sm + CA_XS);
    uint32_t (*Wrc)[132] = (uint32_t(*)[132])(sm + CA_WRC);
    float    (*Zcf)[132] = (float(*)[132])(sm + CA_ZCF);
    uint32_t (*Zcb)[68]  = (uint32_t(*)[68])(sm + CA_ZCB);
    uint32_t (*Gc)[132]  = (uint32_t(*)[132])(sm + CA_GC);

    const int b = blockIdx.x;
    const int tid = threadIdx.x;
    const int lane = tid & 31, wid = tid >> 5;
    const int wm = wid & 3, wn = wid >> 2;
    const int g = lane >> 2, q = lane & 3;

#pragma unroll
    for (int i = 0; i < 8; i++)
        adjs[i * 512 + tid] = g_adj[b * 4096 + i * 512 + tid];

    {
        const int row = tid >> 3;
        const int off = (tid & 7) * 8;
#pragma unroll
        for (int u = 0; u < 2; u++) {
            const int o = off + u * 4;
            float4 v = *(const float4*)(x + (size_t)(b * 64 + row) * 64 + o);
            uint32_t h01, l01, h23, l23;
            split2(v.x, v.y, h01, l01);
            split2(v.z, v.w, h23, l23);
            const int p = o >> 1;
            Xs[row][p]          = h01;
            Xs[row][p + 1]      = h23;
            Xs[row][32 + p]     = l01;
            Xs[row][32 + p + 1] = l23;
        }
    }
    __syncthreads();

    float acc2[2][4] = {};
    const int pc = tid >> 4;
    const int wcolb = (tid & 15) * 8;

#pragma unroll 1
    for (int t = 0; t < 32; t++) {
        const int k0 = 2 * t;
#pragma unroll
        for (int u = 0; u < 2; u++) {
            const int col = wcolb + u * 4;
            const int k = k0 + (col >> 6);
            const int d = col & 63;
            const float* wp = Wagg + ((size_t)k * 64 + 2 * pc) * 64 + d;
            float4 r0 = *(const float4*)(wp);
            float4 r1 = *(const float4*)(wp + 64);
            uint32_t h, l;
            split2(r0.x, r1.x, h, l); Wrc[pc][col]     = h; Wrc[32 + pc][col]     = l;
            split2(r0.y, r1.y, h, l); Wrc[pc][col + 1] = h; Wrc[32 + pc][col + 1] = l;
            split2(r0.z, r1.z, h, l); Wrc[pc][col + 2] = h; Wrc[32 + pc][col + 2] = l;
            split2(r0.w, r1.w, h, l); Wrc[pc][col + 3] = h; Wrc[32 + pc][col + 3] = l;
        }
#pragma unroll
        for (int it = 0; it < 8; it++) {
            const int idx = it * 512 + tid;
            const int i = idx >> 6, j = idx & 63;
            const int e = adjs[idx];
            float v0 = 0.f, v1 = 0.f;
            if (e >= 0) {
                v0 = CoutT[(size_t)k0 * EE + e];
                v1 = CoutT[(size_t)(k0 + 1) * EE + e];
            }
            uint32_t h, l;
            split2(v0, v1, h, l);
            Gc[i][j]      = h;
            Gc[i][64 + j] = l;
        }
        __syncthreads();

        {
            float acc1[4][4] = {};
            const int row = wm * 16 + g;
#pragma unroll
            for (int ks = 0; ks < 4; ks++) {
                uint32_t ah[4], al[4];
                ah[0] = Xs[row][ks * 8 + q];       ah[1] = Xs[row + 8][ks * 8 + q];
                ah[2] = Xs[row][ks * 8 + q + 4];   ah[3] = Xs[row + 8][ks * 8 + q + 4];
                al[0] = Xs[row][32 + ks * 8 + q];     al[1] = Xs[row + 8][32 + ks * 8 + q];
                al[2] = Xs[row][32 + ks * 8 + q + 4]; al[3] = Xs[row + 8][32 + ks * 8 + q + 4];
#pragma unroll
                for (int nt = 0; nt < 4; nt++) {
                    const int col = wn * 32 + nt * 8 + g;
                    uint32_t bh[2] = {Wrc[ks * 8 + q][col], Wrc[ks * 8 + q + 4][col]};
                    uint32_t bl[2] = {Wrc[32 + ks * 8 + q][col], Wrc[32 + ks * 8 + q + 4][col]};
                    mma16(acc1[nt], ah, bh);
                    mma16(acc1[nt], ah, bl);
                    mma16(acc1[nt], al, bh);
                }
            }
#pragma unroll
            for (int nt = 0; nt < 4; nt++) {
                const int col = wn * 32 + nt * 8 + 2 * q;
                *(float2*)(&Zcf[row][col])     = make_float2(acc1[nt][0], acc1[nt][1]);
                *(float2*)(&Zcf[row + 8][col]) = make_float2(acc1[nt][2], acc1[nt][3]);
            }
        }
        __syncthreads();

#pragma unroll
        for (int it = 0; it < 8; it++) {
            const int idx = it * 512 + tid;
            const int j = idx >> 6, d = idx & 63;
            uint32_t h, l;
            split2(Zcf[j][d], Zcf[j][64 + d], h, l);
            Zcb[j][d]      = h;
            Zcb[64 + j][d] = l;
        }
        __syncthreads();

        {
            const int row = wm * 16 + g;
#pragma unroll
            for (int ks = 0; ks < 8; ks++) {
                uint32_t ah[4], al[4];
                ah[0] = Gc[row][ks * 8 + q];       ah[1] = Gc[row + 8][ks * 8 + q];
                ah[2] = Gc[row][ks * 8 + q + 4];   ah[3] = Gc[row + 8][ks * 8 + q + 4];
                al[0] = Gc[row][64 + ks * 8 + q];     al[1] = Gc[row + 8][64 + ks * 8 + q];
                al[2] = Gc[row][64 + ks * 8 + q + 4]; al[3] = Gc[row + 8][64 + ks * 8 + q + 4];
#pragma unroll
                for (int nt = 0; nt < 2; nt++) {
                    const int col = wn * 16 + nt * 8 + g;
                    uint32_t bh[2] = {Zcb[ks * 8 + q][col], Zcb[ks * 8 + q + 4][col]};
                    uint32_t bl[2] = {Zcb[64 + ks * 8 + q][col], Zcb[64 + ks * 8 + q + 4][col]};
                    mma16(acc2[nt], ah, bh);
                    mma16(acc2[nt], ah, bl);
                    mma16(acc2[nt], al, bh);
                }
            }
        }
        __syncthreads();
    }

    {
        const int row = b * 64 + wm * 16 + g;
#pragma unroll
        for (int nt = 0; nt < 2; nt++) {
            const int col = wn * 16 + nt * 8 + 2 * q;
            *(float2*)(agg + (size_t)row * 64 + col) =
                make_float2(acc2[nt][0], acc2[nt][1]);
            *(float2*)(agg + (size_t)(row + 8) * 64 + col) =
                make_float2(acc2[nt][2], acc2[nt][3]);
        }
    }
}

// -------------------- generic weight pair packing --------------------
__global__ void k_packW(const float* __restrict__ W, uint2* __restrict__ out,
                        int K, int N) {
    int idx = blockIdx.x * blockDim.x + threadIdx.x;
    if (idx >= (K / 2) * N) return;
    int p = idx / N, col = idx % N;
    uint32_t h, l;
    split2(W[(2 * p) * N + col], W[(2 * p + 1) * N + col], h, l);
    out[idx] = make_uint2(h, l);
}
__global__ void k_pack_w(const float* __restrict__ W1, const float* __restrict__ W2,
                         const float* __restrict__ W3, const float* __restrict__ W4) {
    int idx = blockIdx.x * blockDim.x + threadIdx.x;
    if (idx >= 64 * 256) return;
    int k = idx >> 8, n = idx & 255;
    int sel = n >> 6, col = n & 63;
    const float* W = (sel == 0) ? W1 : (sel == 1) ? W2 : (sel == 2) ? W3 : W4;
    g_wcat[idx] = W[k * 64 + col];
}

// -------------------- adjacency --------------------
__global__ void k_adj_init() {
    int i = blockIdx.x * blockDim.x + threadIdx.x;
    if (i < BB * NL * NL) g_adj[i] = -1;
}
__global__ void k_adj_fill(const int* __restrict__ EI) {
    int e = blockIdx.x * blockDim.x + threadIdx.x;
    if (e >= EE) return;
    int base = EI[e];
    int li = EI[EE + e] - base;
    int lj = EI[2 * EE + e] - base;
    int b = base >> 6;
    g_adj[b * (NL * NL) + li * NL + lj] = e;
}

// -------------------- tmp_mm via out-edge compaction --------------------
__global__ void __launch_bounds__(256) k_mm3() {
    __shared__ int   rowstage[64];
    __shared__ int   kk[16];
    __shared__ int   eo[16];
    __shared__ int   adjs[16][17];
    __shared__ float Xs[16][65];
    const int n = blockIdx.x;
    const int b = n >> 6, li = n & 63;
    const int tid = threadIdx.x;
    const int q = tid >> 6, c = tid & 63;
    const int* badj = g_adj + b * (NL * NL);

    if (tid < 64) rowstage[tid] = badj[li * 64 + tid];
    __syncthreads();
    if (tid == 0) {
        int cnt = 0;
        for (int j = 0; j < 64 && cnt < 16; j++) {
            int e = rowstage[j];
            if (e >= 0) { kk[cnt] = j; eo[cnt] = e; cnt++; }
        }
        for (; cnt < 16; cnt++) { kk[cnt] = -1; eo[cnt] = -1; }
    }
    __syncthreads();
    {
        const int a = tid >> 4, s = tid & 15;
        const int ka = kk[a], ks = kk[s];
        adjs[a][s] = (ka >= 0 && ks >= 0) ? badj[ka * 64 + ks] : -1;
    }
#pragma unroll
    for (int i = 0; i < 4; i++) {
        const int a = q * 4 + i;
        const int e1 = eo[a];
        Xs[a][c] = (e1 >= 0) ? g_e1[(size_t)e1 * 256 + 128 + c] : 0.0f;
    }
    __syncthreads();
#pragma unroll 1
    for (int i = 0; i < 4; i++) {
        const int s = q * 4 + i;
        const int e_out = eo[s];
        if (e_out < 0) continue;
        float acc = 0.0f;
#pragma unroll
        for (int a = 0; a < 16; a++) {
            const int e2 = adjs[a][s];
            if (e2 >= 0) acc += Xs[a][c] * g_e1[(size_t)e2 * 256 + 192 + c];
        }
        g_mm[(size_t)e_out * 64 + c] = acc;
    }
}

// -------------------- launch --------------------
static inline void gemm(const float* A, const float* B, float* C, int M, int N, int K) {
    if (N % 128 == 0) {
        dim3 grd(M / 128, N / 128);
        k_gemm_f16<128><<<grd, 256>>>(A, B, C, M, N, K);
    } else {
        dim3 grd(M / 128, N / 64);
        k_gemm_f16<64><<<grd, 256>>>(A, B, C, M, N, K);
    }
}

extern "C" void kernel_launch(void* const* d_in, const int* in_sizes, int n_in,
                              void* d_out, int out_size) {
    const float* x    = (const float*)d_in[0];
    const float* Cin  = (const float*)d_in[1];
    const float* W1   = (const float*)d_in[2];
    const float* W2   = (const float*)d_in[3];
    const float* W3   = (const float*)d_in[4];
    const float* W4   = (const float*)d_in[5];
    const float* W5   = (const float*)d_in[6];
    const float* We1  = (const float*)d_in[7];
    const float* lneg = (const float*)d_in[8];
    const float* lneb = (const float*)d_in[9];
    const float* We2  = (const float*)d_in[10];
    const float* Wn1  = (const float*)d_in[11];
    const float* lnng = (const float*)d_in[12];
    const float* lnnb = (const float*)d_in[13];
    const float* Wn2  = (const float*)d_in[14];
    const float* Wagg = (const float*)d_in[15];
    const int*   EI   = (const int*)d_in[16];

    float* xout = (float*)d_out;
    float* Cout = (float*)d_out + (size_t)NN * 64;

    cudaFuncSetAttribute(k_edge_mlp, cudaFuncAttributeMaxDynamicSharedMemorySize, SMEM_EDGE);
    cudaFuncSetAttribute(k_node_mlp, cudaFuncAttributeMaxDynamicSharedMemorySize, SMEM_EDGE);
    cudaFuncSetAttribute(k_cagg, cudaFuncAttributeMaxDynamicSharedMemorySize, SMEM_CAGG);

    float *p_h5, *p_e1, *p_mm, *p_ct, *p_agg, *p_wcat;
    uint2 *p_we1p, *p_we2p, *p_wn1p, *p_wn2p;
    cudaGetSymbolAddress((void**)&p_h5, g_h5);
    cudaGetSymbolAddress((void**)&p_e1, g_e1);
    cudaGetSymbolAddress((void**)&p_mm, g_mm);
    cudaGetSymbolAddress((void**)&p_ct, g_ct);
    cudaGetSymbolAddress((void**)&p_agg, g_agg);
    cudaGetSymbolAddress((void**)&p_wcat, g_wcat);
    cudaGetSymbolAddress((void**)&p_we1p, g_we1p);
    cudaGetSymbolAddress((void**)&p_we2p, g_we2p);
    cudaGetSymbolAddress((void**)&p_wn1p, g_wn1p);
    cudaGetSymbolAddress((void**)&p_wn2p, g_wn2p);

    // prep
    k_pack_w<<<(64 * 256 + 255) / 256, 256>>>(W1, W2, W3, W4);
    k_packW<<<(128 * 256 + 255) / 256, 256>>>(We1, p_we1p, 256, 256);
    k_packW<<<(128 * 64 + 255) / 256, 256>>>(We2, p_we2p, 256, 64);
    k_packW<<<(32 * 256 + 255) / 256, 256>>>(Wn1, p_wn1p, 64, 256);
    k_packW<<<(128 * 64 + 255) / 256, 256>>>(Wn2, p_wn2p, 256, 64);
    k_adj_init<<<(BB * NL * NL + 255) / 256, 256>>>();
    k_adj_fill<<<(EE + 255) / 256, 256>>>(EI);

    // pre-GEMMs
    gemm(x,   W5,     p_h5, NN, 64, 64);
    gemm(Cin, p_wcat, p_e1, EE, 256, 64);   // [t1|t2|X3|Y4]

    // tmp_mm
    k_mm3<<<NN, 256>>>();

    // fused edge MLP
    k_edge_mlp<<<EE / 128, 512, SMEM_EDGE>>>(Cin, p_e1, p_h5, p_mm, EI,
                                             p_we1p, p_we2p, Cout, p_ct, lneg, lneb);

    // fused Conv_agg
    k_cagg<<<BB, 512, SMEM_CAGG>>>(x, Wagg, p_ct, p_agg);

    // fused node MLP
    k_node_mlp<<<NN / 128, 512, SMEM_EDGE>>>(p_agg, p_wn1p, p_wn2p, xout, lnng, lnnb);
}

// round 16
// speedup vs baseline: 1.0977x; 1.0232x over previous
#include <cuda_runtime.h>
#include <cuda_fp16.h>
#include <cstdint>
#include <cstddef>

#define BB 128
#define NL 64
#define EE 131072
#define NN 8192
#define KD 4096

// -------------------- device scratch --------------------
__device__ float g_h5 [NN * 64];
__device__ float g_e1 [EE * 256];      // cat[t1|t2|X3|Y4]
__device__ float g_mm [EE * 64];       // tmp_mm result
__device__ float g_ct [64 * EE];       // CoutT
__device__ float g_agg[NN * 64];
__device__ float g_wcat[64 * 256];     // [W1|W2|W3|W4]
__device__ uint2 g_we2p[128 * 64];     // We2 split pairs
__device__ uint2 g_wn1p[32 * 256];     // Wn1 split pairs
__device__ uint2 g_wn2p[128 * 64];     // Wn2 split pairs
__device__ int   g_adj[BB * NL * NL];

// -------------------- mma helpers --------------------
__device__ __forceinline__ void mma16(float* c, const uint32_t* a, const uint32_t* b) {
    asm volatile(
        "mma.sync.aligned.m16n8k16.row.col.f32.f16.f16.f32 "
        "{%0,%1,%2,%3}, {%4,%5,%6,%7}, {%8,%9}, {%0,%1,%2,%3};"
        : "+f"(c[0]), "+f"(c[1]), "+f"(c[2]), "+f"(c[3])
        : "r"(a[0]), "r"(a[1]), "r"(a[2]), "r"(a[3]), "r"(b[0]), "r"(b[1]));
}
__device__ __forceinline__ void split2(float x, float y, uint32_t& h, uint32_t& l) {
    __half2 hh = __floats2half2_rn(x, y);
    float2 hf = __half22float2(hh);
    __half2 ll = __floats2half2_rn(x - hf.x, y - hf.y);
    h = *(uint32_t*)&hh;
    l = *(uint32_t*)&ll;
}

// ==================== split-FP16 3-term mma.sync GEMM (standalone) ====================
#define APAD2 36

template<int NT>
__global__ void __launch_bounds__(256, 2) k_gemm_f16(const float* __restrict__ A,
                                                     const float* __restrict__ B,
                                                     float* __restrict__ C,
                                                     int M, int N, int K) {
    constexpr int BPAD2 = (NT == 64) ? 72 : 136;
    constexpr int NTW = NT / 16;
    __shared__ uint32_t As2[128][APAD2];
    __shared__ uint32_t Bs2[32][BPAD2];
    const int tid = threadIdx.x;
    const int lane = tid & 31, wid = tid >> 5;
    const int wm = wid & 3, wn = wid >> 2;
    const int g = lane >> 2, q = lane & 3;
    const int m0 = blockIdx.x * 128, n0 = blockIdx.y * NT;

    const int ar = tid >> 3;
    const int ac = (tid & 7) * 4;
    const int ap = ac >> 1;
    constexpr int BTPR = NT / 4;
    const int bp = tid / BTPR;
    const int bn = (tid % BTPR) * 4;

    float acc[2][NTW][4] = {};

    for (int k0 = 0; k0 < K; k0 += 32) {
#pragma unroll
        for (int i = 0; i < 4; i++) {
            const int row = ar + i * 32;
            float4 v = *(const float4*)(A + (size_t)(m0 + row) * K + k0 + ac);
            uint32_t h01, l01, h23, l23;
            split2(v.x, v.y, h01, l01);
            split2(v.z, v.w, h23, l23);
            As2[row][ap]      = h01;
            As2[row][ap + 1]  = h23;
            As2[row][ap + 16] = l01;
            As2[row][ap + 17] = l23;
        }
#pragma unroll
        for (int it = 0; it < NT / 64; it++) {
            const int p = bp + it * 8;
            const float* r0p = B + (size_t)(k0 + 2 * p) * N + n0 + bn;
            float4 r0 = *(const float4*)(r0p);
            float4 r1 = *(const float4*)(r0p + N);
            uint32_t h, l;
            split2(r0.x, r1.x, h, l); Bs2[p][bn]     = h; Bs2[p + 16][bn]     = l;
            split2(r0.y, r1.y, h, l); Bs2[p][bn + 1] = h; Bs2[p + 16][bn + 1] = l;
            split2(r0.z, r1.z, h, l); Bs2[p][bn + 2] = h; Bs2[p + 16][bn + 2] = l;
            split2(r0.w, r1.w, h, l); Bs2[p][bn + 3] = h; Bs2[p + 16][bn + 3] = l;
        }
        __syncthreads();

#pragma unroll
        for (int s = 0; s < 2; s++) {
            uint32_t ah[2][4], al[2][4];
#pragma unroll
            for (int mt = 0; mt < 2; mt++) {
                const int row = wm * 32 + mt * 16 + g;
                ah[mt][0] = As2[row][s * 8 + q];
                ah[mt][1] = As2[row + 8][s * 8 + q];
                ah[mt][2] = As2[row][s * 8 + q + 4];
                ah[mt][3] = As2[row + 8][s * 8 + q + 4];
                al[mt][0] = As2[row][16 + s * 8 + q];
                al[mt][1] = As2[row + 8][16 + s * 8 + q];
                al[mt][2] = As2[row][16 + s * 8 + q + 4];
                al[mt][3] = As2[row + 8][16 + s * 8 + q + 4];
            }
#pragma unroll
            for (int nt = 0; nt < NTW; nt++) {
                const int col = wn * (NT / 2) + nt * 8 + g;
                uint32_t bh[2], bl[2];
                bh[0] = Bs2[s * 8 + q][col];
                bh[1] = Bs2[s * 8 + q + 4][col];
                bl[0] = Bs2[16 + s * 8 + q][col];
                bl[1] = Bs2[16 + s * 8 + q + 4][col];
#pragma unroll
                for (int mt = 0; mt < 2; mt++) {
                    mma16(acc[mt][nt], ah[mt], bh);
                    mma16(acc[mt][nt], ah[mt], bl);
                    mma16(acc[mt][nt], al[mt], bh);
                }
            }
        }
        __syncthreads();
    }

#pragma unroll
    for (int mt = 0; mt < 2; mt++) {
        const int row = m0 + wm * 32 + mt * 16 + g;
#pragma unroll
        for (int nt = 0; nt < NTW; nt++) {
            const int col = n0 + wn * (NT / 2) + nt * 8 + q * 2;
            *(float2*)(C + (size_t)row * N + col) =
                make_float2(acc[mt][nt][0], acc[mt][nt][1]);
            *(float2*)(C + (size_t)(row + 8) * N + col) =
                make_float2(acc[mt][nt][2], acc[mt][nt][3]);
        }
    }
}

// ==================== fused edge MLP, 512 thr (exact R13 structure) ====================
#define HIDS 264
#define BW1  264
#define SM_AS2 0
#define SM_BS2 4608
#define SM_HID (SM_BS2 + 32 * BW1)
#define SM_RST (SM_HID + 128 * HIDS)
#define SM_GB  (SM_RST + 256)
#define SM_EDGE_WORDS (SM_GB + 512)
#define SMEM_EDGE (SM_EDGE_WORDS * 4)
#define TS 132

__global__ void __launch_bounds__(512) k_edge_mlp(const float* __restrict__ Cin,
                                                  const float* __restrict__ cat,
                                                  const float* __restrict__ h5,
                                                  const float* __restrict__ mm,
                                                  const int* __restrict__ EI,
                                                  const float* __restrict__ B,
                                                  const uint2* __restrict__ B2,
                                                  float* __restrict__ Cout,
                                                  float* __restrict__ CoutT,
                                                  const float* __restrict__ gam,
                                                  const float* __restrict__ bet) {
    extern __shared__ uint32_t sm[];
    uint32_t (*As2)[36]  = (uint32_t(*)[36])(sm + SM_AS2);
    uint32_t (*Bs2)[BW1] = (uint32_t(*)[BW1])(sm + SM_BS2);
    uint32_t* hidw = sm + SM_HID;
    float*    hidf = (float*)hidw;
    float*    rstat = (float*)(sm + SM_RST);
    float*    gb    = (float*)(sm + SM_GB);

    const int tid = threadIdx.x;
    const int lane = tid & 31, wid = tid >> 5;   // 16 warps
    const int wm = wid & 3, wn = wid >> 2;       // 4 x 4
    const int g = lane >> 2, q = lane & 3;
    const int m0 = blockIdx.x * 128;

    if (tid < 256) {
        gb[2 * tid]     = gam[tid];
        gb[2 * tid + 1] = bet[tid];
    }

    const int ar = tid >> 2;            // 0..127
    const int ac = (tid & 3) * 8;       // 0,8,16,24
    const int ap = ac >> 1;             // 0,4,8,12
    const int bp = tid >> 5;            // 0..15
    const int bn = (tid & 31) * 8;      // 0..248

    int sl;
    {
        const int e = m0 + ar;
        const int s = EI[EE + e], d = EI[2 * EE + e];
        sl = (s == d) ? s : -1;
    }

    // ---------------- GEMM1: hidden = tmp @ We1, single pass, N=256 ----------------
    float acc[2][8][4] = {};
#pragma unroll 1
    for (int c = 0; c < 8; c++) {
        const int k0 = c * 32;
        {   // A synthesis + split
            const size_t e = (size_t)(m0 + ar);
            float4 v0, v1;
            if (c < 2) {
                const float* p = Cin + e * 64 + k0 + ac;
                v0 = *(const float4*)(p);
                v1 = *(const float4*)(p + 4);
            } else if (c < 4) {
                const float* p1 = cat + e * 256 + (k0 - 64) + ac;
                const float* p2 = p1 + 64;
                float4 a0 = *(const float4*)(p1);
                float4 a1 = *(const float4*)(p1 + 4);
                float4 b0 = *(const float4*)(p2);
                float4 b1 = *(const float4*)(p2 + 4);
                v0 = make_float4(a0.x * b0.x, a0.y * b0.y, a0.z * b0.z, a0.w * b0.w);
                v1 = make_float4(a1.x * b1.x, a1.y * b1.y, a1.z * b1.z, a1.w * b1.w);
            } else if (c < 6) {
                if (sl >= 0) {
                    const float* p = h5 + (size_t)sl * 64 + (k0 - 128) + ac;
                    v0 = *(const float4*)(p);
                    v1 = *(const float4*)(p + 4);
                } else {
                    v0 = make_float4(0.f, 0.f, 0.f, 0.f);
                    v1 = v0;
                }
            } else {
                const float* p = mm + e * 64 + (k0 - 192) + ac;
                v0 = *(const float4*)(p);
                v1 = *(const float4*)(p + 4);
            }
            uint32_t h, l;
            split2(v0.x, v0.y, h, l); As2[ar][ap]      = h; As2[ar][ap + 16] = l;
            split2(v0.z, v0.w, h, l); As2[ar][ap + 1]  = h; As2[ar][ap + 17] = l;
            split2(v1.x, v1.y, h, l); As2[ar][ap + 2]  = h; As2[ar][ap + 18] = l;
            split2(v1.z, v1.w, h, l); As2[ar][ap + 3]  = h; As2[ar][ap + 19] = l;
        }
        {   // B staging from float We1 (inline split, R13 style)
            const float* r0p = B + (size_t)(k0 + 2 * bp) * 256 + bn;
            float4 r0a = *(const float4*)(r0p);
            float4 r0b = *(const float4*)(r0p + 4);
            float4 r1a = *(const float4*)(r0p + 256);
            float4 r1b = *(const float4*)(r0p + 260);
            uint4 H, L;
            split2(r0a.x, r1a.x, H.x, L.x);
            split2(r0a.y, r1a.y, H.y, L.y);
            split2(r0a.z, r1a.z, H.z, L.z);
            split2(r0a.w, r1a.w, H.w, L.w);
            *(uint4*)&Bs2[bp][bn]      = H;
            *(uint4*)&Bs2[bp + 16][bn] = L;
            split2(r0b.x, r1b.x, H.x, L.x);
            split2(r0b.y, r1b.y, H.y, L.y);
            split2(r0b.z, r1b.z, H.z, L.z);
            split2(r0b.w, r1b.w, H.w, L.w);
            *(uint4*)&Bs2[bp][bn + 4]      = H;
            *(uint4*)&Bs2[bp + 16][bn + 4] = L;
        }
        __syncthreads();
#pragma unroll
        for (int s = 0; s < 2; s++) {
            uint32_t ah[2][4], al[2][4];
#pragma unroll
            for (int mt = 0; mt < 2; mt++) {
                const int row = wm * 32 + mt * 16 + g;
                ah[mt][0] = As2[row][s * 8 + q];
                ah[mt][1] = As2[row + 8][s * 8 + q];
                ah[mt][2] = As2[row][s * 8 + q + 4];
                ah[mt][3] = As2[row + 8][s * 8 + q + 4];
                al[mt][0] = As2[row][16 + s * 8 + q];
                al[mt][1] = As2[row + 8][16 + s * 8 + q];
                al[mt][2] = As2[row][16 + s * 8 + q + 4];
                al[mt][3] = As2[row + 8][16 + s * 8 + q + 4];
            }
#pragma unroll
            for (int nt = 0; nt < 8; nt++) {
                const int col = wn * 64 + nt * 8 + g;
                uint32_t bh[2], bl[2];
                bh[0] = Bs2[s * 8 + q][col];
                bh[1] = Bs2[s * 8 + q + 4][col];
                bl[0] = Bs2[16 + s * 8 + q][col];
                bl[1] = Bs2[16 + s * 8 + q + 4][col];
#pragma unroll
                for (int mt = 0; mt < 2; mt++) {
                    mma16(acc[mt][nt], ah[mt], bh);
                    mma16(acc[mt][nt], ah[mt], bl);
                    mma16(acc[mt][nt], al[mt], bh);
                }
            }
        }
        __syncthreads();
    }
    // park raw hidden
#pragma unroll
    for (int mt = 0; mt < 2; mt++) {
        const int row = wm * 32 + mt * 16 + g;
#pragma unroll
        for (int nt = 0; nt < 8; nt++) {
            const int col = wn * 64 + nt * 8 + 2 * q;
            *(float2*)(hidf + (size_t)row * HIDS + col) =
                make_float2(acc[mt][nt][0], acc[mt][nt][1]);
            *(float2*)(hidf + (size_t)(row + 8) * HIDS + col) =
                make_float2(acc[mt][nt][2], acc[mt][nt][3]);
        }
    }
    __syncthreads();

    // ---------------- LN stats ----------------
#pragma unroll 1
    for (int rr = 0; rr < 8; rr++) {
        const int row = wid * 8 + rr;
        float s1 = 0.f, s2 = 0.f;
#pragma unroll
        for (int j = 0; j < 8; j++) {
            float v = hidf[(size_t)row * HIDS + lane + 32 * j];
            s1 += v; s2 += v * v;
        }
#pragma unroll
        for (int o = 16; o > 0; o >>= 1) {
            s1 += __shfl_xor_sync(0xffffffffu, s1, o);
            s2 += __shfl_xor_sync(0xffffffffu, s2, o);
        }
        if (lane == 0) {
            float mu = s1 * (1.0f / 256.0f);
            float var = fmaxf(s2 * (1.0f / 256.0f) - mu * mu, 0.f);
            rstat[2 * row]     = mu;
            rstat[2 * row + 1] = rsqrtf(var + 1e-5f);
        }
    }
    __syncthreads();

    // ---------------- LN + GELU + split-pack, in place ----------------
#pragma unroll 1
    for (int i = 0; i < 32; i++) {
        const int idx = i * 512 + tid;
        const int r = idx >> 7, p = idx & 127;
        float2 v = *(float2*)(hidf + (size_t)r * HIDS + 2 * p);
        const float mu = rstat[2 * r], rs = rstat[2 * r + 1];
        float4 gbv = *(float4*)(gb + 4 * p);
        float y0 = (v.x - mu) * rs * gbv.x + gbv.y;
        float y1 = (v.y - mu) * rs * gbv.z + gbv.w;
        y0 = 0.5f * y0 * (1.0f + erff(y0 * 0.70710678118654752440f));
        y1 = 0.5f * y1 * (1.0f + erff(y1 * 0.70710678118654752440f));
        uint32_t h, l;
        split2(y0, y1, h, l);
        hidw[(size_t)r * HIDS + 2 * p]     = h;
        hidw[(size_t)r * HIDS + 2 * p + 1] = l;
    }
    __syncthreads();

    // ---------------- GEMM2: Cout = hidden @ We2 ----------------
    float acc2[2][2][4] = {};
#pragma unroll 1
    for (int s = 0; s < 16; s++) {
        uint32_t ah[2][4], al[2][4];
#pragma unroll
        for (int mt = 0; mt < 2; mt++) {
            const int row = wm * 32 + mt * 16 + g;
            uint2 t0 = *(uint2*)(hidw + (size_t)row * HIDS + 16 * s + 2 * q);
            uint2 t1 = *(uint2*)(hidw + (size_t)(row + 8) * HIDS + 16 * s + 2 * q);
            uint2 t2 = *(uint2*)(hidw + (size_t)row * HIDS + 16 * s + 2 * q + 8);
            uint2 t3 = *(uint2*)(hidw + (size_t)(row + 8) * HIDS + 16 * s + 2 * q + 8);
            ah[mt][0] = t0.x; al[mt][0] = t0.y;
            ah[mt][1] = t1.x; al[mt][1] = t1.y;
            ah[mt][2] = t2.x; al[mt][2] = t2.y;
            ah[mt][3] = t3.x; al[mt][3] = t3.y;
        }
#pragma unroll
        for (int nt = 0; nt < 2; nt++) {
            const int col = wn * 16 + nt * 8 + g;
            uint2 u0 = __ldg(&B2[(8 * s + q) * 64 + col]);
            uint2 u1 = __ldg(&B2[(8 * s + q + 4) * 64 + col]);
            uint32_t bh[2] = {u0.x, u1.x};
            uint32_t bl[2] = {u0.y, u1.y};
#pragma unroll
            for (int mt = 0; mt < 2; mt++) {
                mma16(acc2[mt][nt], ah[mt], bh);
                mma16(acc2[mt][nt], ah[mt], bl);
                mma16(acc2[mt][nt], al[mt], bh);
            }
        }
    }
    __syncthreads();

    float* T = (float*)(sm + SM_HID);
#pragma unroll
    for (int mt = 0; mt < 2; mt++) {
        const int rloc = wm * 32 + mt * 16 + g;
        const int row = m0 + rloc;
#pragma unroll
        for (int nt = 0; nt < 2; nt++) {
            const int col = wn * 16 + nt * 8 + 2 * q;
            *(float2*)(Cout + (size_t)row * 64 + col) =
                make_float2(acc2[mt][nt][0], acc2[mt][nt][1]);
            *(float2*)(Cout + (size_t)(row + 8) * 64 + col) =
                make_float2(acc2[mt][nt][2], acc2[mt][nt][3]);
            T[col * TS + rloc]           = acc2[mt][nt][0];
            T[(col + 1) * TS + rloc]     = acc2[mt][nt][1];
            T[col * TS + rloc + 8]       = acc2[mt][nt][2];
            T[(col + 1) * TS + rloc + 8] = acc2[mt][nt][3];
        }
    }
    __syncthreads();
#pragma unroll
    for (int i = 0; i < 16; i++) {
        const int idx = i * 512 + tid;
        const int k = idx >> 7, r = idx & 127;
        CoutT[(size_t)k * EE + m0 + r] = T[k * TS + r];
    }
}

// ==================== fused node MLP, 512 thr ====================
__global__ void __launch_bounds__(512) k_node_mlp(const float* __restrict__ A,
                                                  const uint2* __restrict__ B1,
                                                  const uint2* __restrict__ B2,
                                                  float* __restrict__ xout,
                                                  const float* __restrict__ gam,
                                                  const float* __restrict__ bet) {
    extern __shared__ uint32_t sm[];
    uint32_t (*As2)[36]  = (uint32_t(*)[36])(sm + SM_AS2);
    uint32_t (*Bs2)[BW1] = (uint32_t(*)[BW1])(sm + SM_BS2);
    uint32_t* hidw = sm + SM_HID;
    float*    hidf = (float*)hidw;
    float*    rstat = (float*)(sm + SM_RST);
    float*    gb    = (float*)(sm + SM_GB);

    const int tid = threadIdx.x;
    const int lane = tid & 31, wid = tid >> 5;
    const int wm = wid & 3, wn = wid >> 2;
    const int g = lane >> 2, q = lane & 3;
    const int m0 = blockIdx.x * 128;

    if (tid < 256) {
        gb[2 * tid]     = gam[tid];
        gb[2 * tid + 1] = bet[tid];
    }

    const int ar = tid >> 2;
    const int ac = (tid & 3) * 8;
    const int ap = ac >> 1;
    const int bp = tid >> 5;
    const int bn = (tid & 31) * 8;

    // ---------------- GEMM1: hid = agg @ Wn1 (K=64: 2 chunks) ----------------
    float acc[2][8][4] = {};
#pragma unroll 1
    for (int c = 0; c < 2; c++) {
        const int k0 = c * 32;
        {
            const float* p = A + (size_t)(m0 + ar) * 64 + k0 + ac;
            float4 v0 = *(const float4*)(p);
            float4 v1 = *(const float4*)(p + 4);
            uint32_t h, l;
            split2(v0.x, v0.y, h, l); As2[ar][ap]      = h; As2[ar][ap + 16] = l;
            split2(v0.z, v0.w, h, l); As2[ar][ap + 1]  = h; As2[ar][ap + 17] = l;
            split2(v1.x, v1.y, h, l); As2[ar][ap + 2]  = h; As2[ar][ap + 18] = l;
            split2(v1.z, v1.w, h, l); As2[ar][ap + 3]  = h; As2[ar][ap + 19] = l;
        }
        {
            const uint2* src = B1 + (size_t)(c * 16 + bp) * 256 + bn;
            uint4 w0 = *(const uint4*)(src);
            uint4 w1 = *(const uint4*)(src + 2);
            uint4 w2 = *(const uint4*)(src + 4);
            uint4 w3 = *(const uint4*)(src + 6);
            *(uint4*)&Bs2[bp][bn]          = make_uint4(w0.x, w0.z, w1.x, w1.z);
            *(uint4*)&Bs2[bp + 16][bn]     = make_uint4(w0.y, w0.w, w1.y, w1.w);
            *(uint4*)&Bs2[bp][bn + 4]      = make_uint4(w2.x, w2.z, w3.x, w3.z);
            *(uint4*)&Bs2[bp + 16][bn + 4] = make_uint4(w2.y, w2.w, w3.y, w3.w);
        }
        __syncthreads();
#pragma unroll
        for (int s = 0; s < 2; s++) {
            uint32_t ah[2][4], al[2][4];
#pragma unroll
            for (int mt = 0; mt < 2; mt++) {
                const int row = wm * 32 + mt * 16 + g;
                ah[mt][0] = As2[row][s * 8 + q];
                ah[mt][1] = As2[row + 8][s * 8 + q];
                ah[mt][2] = As2[row][s * 8 + q + 4];
                ah[mt][3] = As2[row + 8][s * 8 + q + 4];
                al[mt][0] = As2[row][16 + s * 8 + q];
                al[mt][1] = As2[row + 8][16 + s * 8 + q];
                al[mt][2] = As2[row][16 + s * 8 + q + 4];
                al[mt][3] = As2[row + 8][16 + s * 8 + q + 4];
            }
#pragma unroll
            for (int nt = 0; nt < 8; nt++) {
                const int col = wn * 64 + nt * 8 + g;
                uint32_t bh[2], bl[2];
                bh[0] = Bs2[s * 8 + q][col];
                bh[1] = Bs2[s * 8 + q + 4][col];
                bl[0] = Bs2[16 + s * 8 + q][col];
                bl[1] = Bs2[16 + s * 8 + q + 4][col];
#pragma unroll
                for (int mt = 0; mt < 2; mt++) {
                    mma16(acc[mt][nt], ah[mt], bh);
                    mma16(acc[mt][nt], ah[mt], bl);
                    mma16(acc[mt][nt], al[mt], bh);
                }
            }
        }
        __syncthreads();
    }
#pragma unroll
    for (int mt = 0; mt < 2; mt++) {
        const int row = wm * 32 + mt * 16 + g;
#pragma unroll
        for (int nt = 0; nt < 8; nt++) {
            const int col = wn * 64 + nt * 8 + 2 * q;
            *(float2*)(hidf + (size_t)row * HIDS + col) =
                make_float2(acc[mt][nt][0], acc[mt][nt][1]);
            *(float2*)(hidf + (size_t)(row + 8) * HIDS + col) =
                make_float2(acc[mt][nt][2], acc[mt][nt][3]);
        }
    }
    __syncthreads();

    // ---------------- LN stats ----------------
#pragma unroll 1
    for (int rr = 0; rr < 8; rr++) {
        const int row = wid * 8 + rr;
        float s1 = 0.f, s2 = 0.f;
#pragma unroll
        for (int j = 0; j < 8; j++) {
            float v = hidf[(size_t)row * HIDS + lane + 32 * j];
            s1 += v; s2 += v * v;
        }
#pragma unroll
        for (int o = 16; o > 0; o >>= 1) {
            s1 += __shfl_xor_sync(0xffffffffu, s1, o);
            s2 += __shfl_xor_sync(0xffffffffu, s2, o);
        }
        if (lane == 0) {
            float mu = s1 * (1.0f / 256.0f);
            float var = fmaxf(s2 * (1.0f / 256.0f) - mu * mu, 0.f);
            rstat[2 * row]     = mu;
            rstat[2 * row + 1] = rsqrtf(var + 1e-5f);
        }
    }
    __syncthreads();

    // ---------------- LN + GELU + split-pack ----------------
#pragma unroll 1
    for (int i = 0; i < 32; i++) {
        const int idx = i * 512 + tid;
        const int r = idx >> 7, p = idx & 127;
        float2 v = *(float2*)(hidf + (size_t)r * HIDS + 2 * p);
        const float mu = rstat[2 * r], rs = rstat[2 * r + 1];
        float4 gbv = *(float4*)(gb + 4 * p);
        float y0 = (v.x - mu) * rs * gbv.x + gbv.y;
        float y1 = (v.y - mu) * rs * gbv.z + gbv.w;
        y0 = 0.5f * y0 * (1.0f + erff(y0 * 0.70710678118654752440f));
        y1 = 0.5f * y1 * (1.0f + erff(y1 * 0.70710678118654752440f));
        uint32_t h, l;
        split2(y0, y1, h, l);
        hidw[(size_t)r * HIDS + 2 * p]     = h;
        hidw[(size_t)r * HIDS + 2 * p + 1] = l;
    }
    __syncthreads();

    // ---------------- GEMM2: xout = hid @ Wn2 ----------------
    float acc2[2][2][4] = {};
#pragma unroll 1
    for (int s = 0; s < 16; s++) {
        uint32_t ah[2][4], al[2][4];
#pragma unroll
        for (int mt = 0; mt < 2; mt++) {
            const int row = wm * 32 + mt * 16 + g;
            uint2 t0 = *(uint2*)(hidw + (size_t)row * HIDS + 16 * s + 2 * q);
            uint2 t1 = *(uint2*)(hidw + (size_t)(row + 8) * HIDS + 16 * s + 2 * q);
            uint2 t2 = *(uint2*)(hidw + (size_t)row * HIDS + 16 * s + 2 * q + 8);
            uint2 t3 = *(uint2*)(hidw + (size_t)(row + 8) * HIDS + 16 * s + 2 * q + 8);
            ah[mt][0] = t0.x; al[mt][0] = t0.y;
            ah[mt][1] = t1.x; al[mt][1] = t1.y;
            ah[mt][2] = t2.x; al[mt][2] = t2.y;
            ah[mt][3] = t3.x; al[mt][3] = t3.y;
        }
#pragma unroll
        for (int nt = 0; nt < 2; nt++) {
            const int col = wn * 16 + nt * 8 + g;
            uint2 u0 = __ldg(&B2[(8 * s + q) * 64 + col]);
            uint2 u1 = __ldg(&B2[(8 * s + q + 4) * 64 + col]);
            uint32_t bh[2] = {u0.x, u1.x};
            uint32_t bl[2] = {u0.y, u1.y};
#pragma unroll
            for (int mt = 0; mt < 2; mt++) {
                mma16(acc2[mt][nt], ah[mt], bh);
                mma16(acc2[mt][nt], ah[mt], bl);
                mma16(acc2[mt][nt], al[mt], bh);
            }
        }
    }
#pragma unroll
    for (int mt = 0; mt < 2; mt++) {
        const int row = m0 + wm * 32 + mt * 16 + g;
#pragma unroll
        for (int nt = 0; nt < 2; nt++) {
            const int col = wn * 16 + nt * 8 + 2 * q;
            *(float2*)(xout + (size_t)row * 64 + col) =
                make_float2(acc2[mt][nt][0], acc2[mt][nt][1]);
            *(float2*)(xout + (size_t)(row + 8) * 64 + col) =
                make_float2(acc2[mt][nt][2], acc2[mt][nt][3]);
        }
    }
}

// ==================== fused Conv_agg, 512 threads ==========
#define CA_ADJ 0
#define CA_XS  4096
#define CA_WRC 8448
#define CA_ZCF 16896
#define CA_ZCB 25344
#define CA_GC  34048
#define CA_WORDS 42496
#define SMEM_CAGG (CA_WORDS * 4)

__global__ void __launch_bounds__(512) k_cagg(const float* __restrict__ x,
                                              const float* __restrict__ Wagg,
                                              const float* __restrict__ CoutT,
                                              float* __restrict__ agg) {
    extern __shared__ uint32_t sm[];
    int* adjs = (int*)(sm + CA_ADJ);
    uint32_t (*Xs)[68]   = (uint32_t(*)[68])(sm + CA_XS);
    uint32_t (*Wrc)[132] = (uint32_t(*)[132])(sm + CA_WRC);
    float    (*Zcf)[132] = (float(*)[132])(sm + CA_ZCF);
    uint32_t (*Zcb)[68]  = (uint32_t(*)[68])(sm + CA_ZCB);
    uint32_t (*Gc)[132]  = (uint32_t(*)[132])(sm + CA_GC);

    const int b = blockIdx.x;
    const int tid = threadIdx.x;
    const int lane = tid & 31, wid = tid >> 5;
    const int wm = wid & 3, wn = wid >> 2;
    const int g = lane >> 2, q = lane & 3;

#pragma unroll
    for (int i = 0; i < 8; i++)
        adjs[i * 512 + tid] = g_adj[b * 4096 + i * 512 + tid];

    {
        const int row = tid >> 3;
        const int off = (tid & 7) * 8;
#pragma unroll
        for (int u = 0; u < 2; u++) {
            const int o = off + u * 4;
            float4 v = *(const float4*)(x + (size_t)(b * 64 + row) * 64 + o);
            uint32_t h01, l01, h23, l23;
            split2(v.x, v.y, h01, l01);
            split2(v.z, v.w, h23, l23);
            const int p = o >> 1;
            Xs[row][p]          = h01;
            Xs[row][p + 1]      = h23;
            Xs[row][32 + p]     = l01;
            Xs[row][32 + p + 1] = l23;
        }
    }
    __syncthreads();

    float acc2[2][4] = {};
    const int pc = tid >> 4;
    const int wcolb = (tid & 15) * 8;

#pragma unroll 1
    for (int t = 0; t < 32; t++) {
        const int k0 = 2 * t;
#pragma unroll
        for (int u = 0; u < 2; u++) {
            const int col = wcolb + u * 4;
            const int k = k0 + (col >> 6);
            const int d = col & 63;
            const float* wp = Wagg + ((size_t)k * 64 + 2 * pc) * 64 + d;
            float4 r0 = *(const float4*)(wp);
            float4 r1 = *(const float4*)(wp + 64);
            uint32_t h, l;
            split2(r0.x, r1.x, h, l); Wrc[pc][col]     = h; Wrc[32 + pc][col]     = l;
            split2(r0.y, r1.y, h, l); Wrc[pc][col + 1] = h; Wrc[32 + pc][col + 1] = l;
            split2(r0.z, r1.z, h, l); Wrc[pc][col + 2] = h; Wrc[32 + pc][col + 2] = l;
            split2(r0.w, r1.w, h, l); Wrc[pc][col + 3] = h; Wrc[32 + pc][col + 3] = l;
        }
#pragma unroll
        for (int it = 0; it < 8; it++) {
            const int idx = it * 512 + tid;
            const int i = idx >> 6, j = idx & 63;
            const int e = adjs[idx];
            float v0 = 0.f, v1 = 0.f;
            if (e >= 0) {
                v0 = CoutT[(size_t)k0 * EE + e];
                v1 = CoutT[(size_t)(k0 + 1) * EE + e];
            }
            uint32_t h, l;
            split2(v0, v1, h, l);
            Gc[i][j]      = h;
            Gc[i][64 + j] = l;
        }
        __syncthreads();

        {
            float acc1[4][4] = {};
            const int row = wm * 16 + g;
#pragma unroll
            for (int ks = 0; ks < 4; ks++) {
                uint32_t ah[4], al[4];
                ah[0] = Xs[row][ks * 8 + q];       ah[1] = Xs[row + 8][ks * 8 + q];
                ah[2] = Xs[row][ks * 8 + q + 4];   ah[3] = Xs[row + 8][ks * 8 + q + 4];
                al[0] = Xs[row][32 + ks * 8 + q];     al[1] = Xs[row + 8][32 + ks * 8 + q];
                al[2] = Xs[row][32 + ks * 8 + q + 4]; al[3] = Xs[row + 8][32 + ks * 8 + q + 4];
#pragma unroll
                for (int nt = 0; nt < 4; nt++) {
                    const int col = wn * 32 + nt * 8 + g;
                    uint32_t bh[2] = {Wrc[ks * 8 + q][col], Wrc[ks * 8 + q + 4][col]};
                    uint32_t bl[2] = {Wrc[32 + ks * 8 + q][col], Wrc[32 + ks * 8 + q + 4][col]};
                    mma16(acc1[nt], ah, bh);
                    mma16(acc1[nt], ah, bl);
                    mma16(acc1[nt], al, bh);
                }
            }
#pragma unroll
            for (int nt = 0; nt < 4; nt++) {
                const int col = wn * 32 + nt * 8 + 2 * q;
                *(float2*)(&Zcf[row][col])     = make_float2(acc1[nt][0], acc1[nt][1]);
                *(float2*)(&Zcf[row + 8][col]) = make_float2(acc1[nt][2], acc1[nt][3]);
            }
        }
        __syncthreads();

#pragma unroll
        for (int it = 0; it < 8; it++) {
            const int idx = it * 512 + tid;
            const int j = idx >> 6, d = idx & 63;
            uint32_t h, l;
            split2(Zcf[j][d], Zcf[j][64 + d], h, l);
            Zcb[j][d]      = h;
            Zcb[64 + j][d] = l;
        }
        __syncthreads();

        {
            const int row = wm * 16 + g;
#pragma unroll
            for (int ks = 0; ks < 8; ks++) {
                uint32_t ah[4], al[4];
                ah[0] = Gc[row][ks * 8 + q];       ah[1] = Gc[row + 8][ks * 8 + q];
                ah[2] = Gc[row][ks * 8 + q + 4];   ah[3] = Gc[row + 8][ks * 8 + q + 4];
                al[0] = Gc[row][64 + ks * 8 + q];     al[1] = Gc[row + 8][64 + ks * 8 + q];
                al[2] = Gc[row][64 + ks * 8 + q + 4]; al[3] = Gc[row + 8][64 + ks * 8 + q + 4];
#pragma unroll
                for (int nt = 0; nt < 2; nt++) {
                    const int col = wn * 16 + nt * 8 + g;
                    uint32_t bh[2] = {Zcb[ks * 8 + q][col], Zcb[ks * 8 + q + 4][col]};
                    uint32_t bl[2] = {Zcb[64 + ks * 8 + q][col], Zcb[64 + ks * 8 + q + 4][col]};
                    mma16(acc2[nt], ah, bh);
                    mma16(acc2[nt], ah, bl);
                    mma16(acc2[nt], al, bh);
                }
            }
        }
        __syncthreads();
    }

    {
        const int row = b * 64 + wm * 16 + g;
#pragma unroll
        for (int nt = 0; nt < 2; nt++) {
            const int col = wn * 16 + nt * 8 + 2 * q;
            *(float2*)(agg + (size_t)row * 64 + col) =
                make_float2(acc2[nt][0], acc2[nt][1]);
            *(float2*)(agg + (size_t)(row + 8) * 64 + col) =
                make_float2(acc2[nt][2], acc2[nt][3]);
        }
    }
}

// -------------------- generic weight pair packing --------------------
__global__ void k_packW(const float* __restrict__ W, uint2* __restrict__ out,
                        int K, int N) {
    int idx = blockIdx.x * blockDim.x + threadIdx.x;
    if (idx >= (K / 2) * N) return;
    int p = idx / N, col = idx % N;
    uint32_t h, l;
    split2(W[(2 * p) * N + col], W[(2 * p + 1) * N + col], h, l);
    out[idx] = make_uint2(h, l);
}
__global__ void k_pack_w(const float* __restrict__ W1, const float* __restrict__ W2,
                         const float* __restrict__ W3, const float* __restrict__ W4) {
    int idx = blockIdx.x * blockDim.x + threadIdx.x;
    if (idx >= 64 * 256) return;
    int k = idx >> 8, n = idx & 255;
    int sel = n >> 6, col = n & 63;
    const float* W = (sel == 0) ? W1 : (sel == 1) ? W2 : (sel == 2) ? W3 : W4;
    g_wcat[idx] = W[k * 64 + col];
}

// -------------------- adjacency --------------------
__global__ void k_adj_init() {
    int i = blockIdx.x * blockDim.x + threadIdx.x;
    if (i < BB * NL * NL) g_adj[i] = -1;
}
__global__ void k_adj_fill(const int* __restrict__ EI) {
    int e = blockIdx.x * blockDim.x + threadIdx.x;
    if (e >= EE) return;
    int base = EI[e];
    int li = EI[EE + e] - base;
    int lj = EI[2 * EE + e] - base;
    int b = base >> 6;
    g_adj[b * (NL * NL) + li * NL + lj] = e;
}

// -------------------- tmp_mm via out-edge compaction --------------------
__global__ void __launch_bounds__(256) k_mm3() {
    __shared__ int   rowstage[64];
    __shared__ int   kk[16];
    __shared__ int   eo[16];
    __shared__ int   adjs[16][17];
    __shared__ float Xs[16][65];
    const int n = blockIdx.x;
    const int b = n >> 6, li = n & 63;
    const int tid = threadIdx.x;
    const int q = tid >> 6, c = tid & 63;
    const int* badj = g_adj + b * (NL * NL);

    if (tid < 64) rowstage[tid] = badj[li * 64 + tid];
    __syncthreads();
    if (tid == 0) {
        int cnt = 0;
        for (int j = 0; j < 64 && cnt < 16; j++) {
            int e = rowstage[j];
            if (e >= 0) { kk[cnt] = j; eo[cnt] = e; cnt++; }
        }
        for (; cnt < 16; cnt++) { kk[cnt] = -1; eo[cnt] = -1; }
    }
    __syncthreads();
    {
        const int a = tid >> 4, s = tid & 15;
        const int ka = kk[a], ks = kk[s];
        adjs[a][s] = (ka >= 0 && ks >= 0) ? badj[ka * 64 + ks] : -1;
    }
#pragma unroll
    for (int i = 0; i < 4; i++) {
        const int a = q * 4 + i;
        const int e1 = eo[a];
        Xs[a][c] = (e1 >= 0) ? g_e1[(size_t)e1 * 256 + 128 + c] : 0.0f;
    }
    __syncthreads();
#pragma unroll 1
    for (int i = 0; i < 4; i++) {
        const int s = q * 4 + i;
        const int e_out = eo[s];
        if (e_out < 0) continue;
        float acc = 0.0f;
#pragma unroll
        for (int a = 0; a < 16; a++) {
            const int e2 = adjs[a][s];
            if (e2 >= 0) acc += Xs[a][c] * g_e1[(size_t)e2 * 256 + 192 + c];
        }
        g_mm[(size_t)e_out * 64 + c] = acc;
    }
}

// -------------------- launch --------------------
static inline void gemm(const float* A, const float* B, float* C, int M, int N, int K) {
    if (N % 128 == 0) {
        dim3 grd(M / 128, N / 128);
        k_gemm_f16<128><<<grd, 256>>>(A, B, C, M, N, K);
    } else {
        dim3 grd(M / 128, N / 64);
        k_gemm_f16<64><<<grd, 256>>>(A, B, C, M, N, K);
    }
}

extern "C" void kernel_launch(void* const* d_in, const int* in_sizes, int n_in,
                              void* d_out, int out_size) {
    const float* x    = (const float*)d_in[0];
    const float* Cin  = (const float*)d_in[1];
    const float* W1   = (const float*)d_in[2];
    const float* W2   = (const float*)d_in[3];
    const float* W3   = (const float*)d_in[4];
    const float* W4   = (const float*)d_in[5];
    const float* W5   = (const float*)d_in[6];
    const float* We1  = (const float*)d_in[7];
    const float* lneg = (const float*)d_in[8];
    const float* lneb = (const float*)d_in[9];
    const float* We2  = (const float*)d_in[10];
    const float* Wn1  = (const float*)d_in[11];
    const float* lnng = (const float*)d_in[12];
    const float* lnnb = (const float*)d_in[13];
    const float* Wn2  = (const float*)d_in[14];
    const float* Wagg = (const float*)d_in[15];
    const int*   EI   = (const int*)d_in[16];

    float* xout = (float*)d_out;
    float* Cout = (float*)d_out + (size_t)NN * 64;

    cudaFuncSetAttribute(k_edge_mlp, cudaFuncAttributeMaxDynamicSharedMemorySize, SMEM_EDGE);
    cudaFuncSetAttribute(k_node_mlp, cudaFuncAttributeMaxDynamicSharedMemorySize, SMEM_EDGE);
    cudaFuncSetAttribute(k_cagg, cudaFuncAttributeMaxDynamicSharedMemorySize, SMEM_CAGG);

    float *p_h5, *p_e1, *p_mm, *p_ct, *p_agg, *p_wcat;
    uint2 *p_we2p, *p_wn1p, *p_wn2p;
    cudaGetSymbolAddress((void**)&p_h5, g_h5);
    cudaGetSymbolAddress((void**)&p_e1, g_e1);
    cudaGetSymbolAddress((void**)&p_mm, g_mm);
    cudaGetSymbolAddress((void**)&p_ct, g_ct);
    cudaGetSymbolAddress((void**)&p_agg, g_agg);
    cudaGetSymbolAddress((void**)&p_wcat, g_wcat);
    cudaGetSymbolAddress((void**)&p_we2p, g_we2p);
    cudaGetSymbolAddress((void**)&p_wn1p, g_wn1p);
    cudaGetSymbolAddress((void**)&p_wn2p, g_wn2p);

    // prep
    k_pack_w<<<(64 * 256 + 255) / 256, 256>>>(W1, W2, W3, W4);
    k_packW<<<(128 * 64 + 255) / 256, 256>>>(We2, p_we2p, 256, 64);
    k_packW<<<(32 * 256 + 255) / 256, 256>>>(Wn1, p_wn1p, 64, 256);
    k_packW<<<(128 * 64 + 255) / 256, 256>>>(Wn2, p_wn2p, 256, 64);
    k_adj_init<<<(BB * NL * NL + 255) / 256, 256>>>();
    k_adj_fill<<<(EE + 255) / 256, 256>>>(EI);

    // pre-GEMMs
    gemm(x,   W5,     p_h5, NN, 64, 64);
    gemm(Cin, p_wcat, p_e1, EE, 256, 64);   // [t1|t2|X3|Y4]

    // tmp_mm
    k_mm3<<<NN, 256>>>();

    // fused edge MLP (R13-exact structure)
    k_edge_mlp<<<EE / 128, 512, SMEM_EDGE>>>(Cin, p_e1, p_h5, p_mm, EI,
                                             We1, p_we2p, Cout, p_ct, lneg, lneb);

    // fused Conv_agg
    k_cagg<<<BB, 512, SMEM_CAGG>>>(x, Wagg, p_ct, p_agg);

    // fused node MLP
    k_node_mlp<<<NN / 128, 512, SMEM_EDGE>>>(p_agg, p_wn1p, p_wn2p, xout, lnng, lnnb);
}